// round 13
// baseline (speedup 1.0000x reference)
#include <cuda_runtime.h>
#include <cuda_bf16.h>
#include <cstdint>

#define NA 16
#define NEN 128
#define ED 96
#define HE 128
#define MD 32
#define NH 4
#define HD 32
#define TSTRIDE 132   // fp32 stride (528B)
#define STRB 132      // u32 stride of bf16 tiles (528B)
#define SWST 132

// ---- smem float offsets ----
#define OFF_A    0        // A tile: 128 x 264 bf16 = 67584B
#define OFF_B    16896    // B tile: same (fully dead after v GEMM)
#define OFF_KV   33792    // 64 x 132 fp32 kT/vT; after attnV: s_out + s_x3
#define OFF_W    42240    // 64 x 132 softmax w; after attnV: fc2w staging (4096 fp32)
#define OFF_Q    50688    // 16 x 132 q; after logits: s_attn
#define OFF_EMF  52800
#define OFF_RM   52928
#define OFF_W1   52944
#define OFF_FLAG 52960
#define SMEM_FLOATS 52968
#define SMEM_BYTES (SMEM_FLOATS * 4)

#define TILE_U32 (128 * 132)

struct KParams {
    const float* qs;
    const float* ents;
    const unsigned char* em;
    const float* w[14];
    float* out;
};

__device__ uint32_t g_wt[8 * TILE_U32];

static __device__ __forceinline__ void split2(float a, float b, uint32_t& hi, uint32_t& lo) {
    __nv_bfloat16 ha = __float2bfloat16(a), hb = __float2bfloat16(b);
    float ra = a - __bfloat162float(ha), rb = b - __bfloat162float(hb);
    __nv_bfloat16 la = __float2bfloat16(ra), lb = __float2bfloat16(rb);
    hi = (uint32_t)__bfloat16_as_ushort(ha) | ((uint32_t)__bfloat16_as_ushort(hb) << 16);
    lo = (uint32_t)__bfloat16_as_ushort(la) | ((uint32_t)__bfloat16_as_ushort(lb) << 16);
}

static __device__ __forceinline__ float2 ffma2(float2 a, float2 b, float2 c) {
    unsigned long long au = *reinterpret_cast<unsigned long long*>(&a);
    unsigned long long bu = *reinterpret_cast<unsigned long long*>(&b);
    unsigned long long cu = *reinterpret_cast<unsigned long long*>(&c);
    asm("fma.rn.f32x2 %0, %1, %2, %0;" : "+l"(cu) : "l"(au), "l"(bu));
    return *reinterpret_cast<float2*>(&cu);
}

static __device__ __forceinline__ void ldmat4(uint32_t (&r)[4], uint32_t addr) {
    asm volatile("ldmatrix.sync.aligned.m8n8.x4.shared.b16 {%0,%1,%2,%3}, [%4];"
        : "=r"(r[0]), "=r"(r[1]), "=r"(r[2]), "=r"(r[3]) : "r"(addr));
}

static __device__ __forceinline__ void mma16816(float (&d)[4], const uint32_t (&a)[4],
                                                uint32_t b0, uint32_t b1) {
    asm volatile("mma.sync.aligned.m16n8k16.row.col.f32.bf16.bf16.f32 "
        "{%0,%1,%2,%3}, {%4,%5,%6,%7}, {%8,%9}, {%0,%1,%2,%3};"
        : "+f"(d[0]), "+f"(d[1]), "+f"(d[2]), "+f"(d[3])
        : "r"(a[0]), "r"(a[1]), "r"(a[2]), "r"(a[3]), "r"(b0), "r"(b1));
}

static __device__ __forceinline__ void cp_async16(uint32_t saddr, const void* g) {
    asm volatile("cp.async.cg.shared.global [%0], [%1], 16;" :: "r"(saddr), "l"(g));
}

static __device__ __forceinline__ void copyB_async(uint32_t base, const uint32_t* g, int tid) {
#pragma unroll 1
    for (int i = tid; i < TILE_U32 / 4; i += 256)
        cp_async16(base + (uint32_t)i * 16u, g + i * 4);
    asm volatile("cp.async.commit_group;" ::: "memory");
}
#define CP_WAIT0() asm volatile("cp.async.wait_group 0;" ::: "memory")

// Split-3 bf16 GEMM, warp tile 32x64.
template<int K>
static __device__ __forceinline__ void gemm_mma(uint32_t aL, uint32_t bL, float (&acc)[2][8][4]) {
#pragma unroll
    for (int i = 0; i < 2; ++i)
#pragma unroll
        for (int j = 0; j < 8; ++j)
#pragma unroll
            for (int r = 0; r < 4; ++r) acc[i][j][r] = 0.f;
#pragma unroll
    for (int pass = 0; pass < 3; ++pass) {
        const uint32_t aO = (pass == 2) ? (uint32_t)(K * 2) : 0u;
        const uint32_t bO = (pass == 1) ? (uint32_t)(K * 2) : 0u;
#pragma unroll
        for (int kb = 0; kb < K * 2; kb += 32) {
            uint32_t a[2][4], bb[4][4];
            ldmat4(a[0], aL + aO + kb);
            ldmat4(a[1], aL + 16u * 528u + aO + kb);
#pragma unroll
            for (int nj = 0; nj < 4; ++nj)
                ldmat4(bb[nj], bL + (uint32_t)nj * 16u * 528u + bO + kb);
#pragma unroll
            for (int mi = 0; mi < 2; ++mi)
#pragma unroll
                for (int nj = 0; nj < 4; ++nj) {
                    mma16816(acc[mi][2 * nj],     a[mi], bb[nj][0], bb[nj][1]);
                    mma16816(acc[mi][2 * nj + 1], a[mi], bb[nj][2], bb[nj][3]);
                }
        }
    }
}

// ---- prep kernel: split weights into tile-image layout ----
__global__ void prep_kernel(KParams P) {
    const int t = blockIdx.y;
    const int p = t >> 2, ch = t & 3;
    const float* W; int ldb, KP;
    if (ch == 0) { W = P.w[p * 7 + 0]; ldb = HE;     KP = ED / 2; }
    else         { W = P.w[p * 7 + 2] + (ch - 1) * HE; ldb = 3 * HE; KP = 64; }
    uint32_t* dst = g_wt + t * TILE_U32;
    const int nkpb = KP >> 2;
    int idx = blockIdx.x * blockDim.x + threadIdx.x;
    if (idx >= 128 * nkpb) return;
    int n = idx / nkpb, kpb = idx % nkpb;
    uint32_t hi[4], lo[4];
#pragma unroll
    for (int j = 0; j < 4; ++j) {
        int kp = kpb * 4 + j;
        float w0 = __ldg(W + (size_t)(2 * kp) * ldb + n);
        float w1 = __ldg(W + (size_t)(2 * kp + 1) * ldb + n);
        split2(w0, w1, hi[j], lo[j]);
    }
    *reinterpret_cast<uint4*>(dst + n * STRB + kpb * 4)      = make_uint4(hi[0], hi[1], hi[2], hi[3]);
    *reinterpret_cast<uint4*>(dst + n * STRB + KP + kpb * 4) = make_uint4(lo[0], lo[1], lo[2], lo[3]);
}

__global__ void __launch_bounds__(256, 1)
mixer_kernel(KParams P) {
    extern __shared__ float smem[];
    uint32_t* Au    = reinterpret_cast<uint32_t*>(smem + OFF_A);
    float*    s_kv  = smem + OFF_KV;
    float*    s_w   = smem + OFF_W;
    float*    s_q   = smem + OFF_Q;
    float*    s_emf = smem + OFF_EMF;
    float*    s_rm  = smem + OFF_RM;
    float*    s_w1m = smem + OFF_W1;
    float*    s_flag= smem + OFF_FLAG;
    float*    s_attn= smem + OFF_Q;          // reuses q region (dead after logits)
    float*    s_out = smem + OFF_KV;         // reuses kv region (dead after attnV)
    float*    s_x3  = smem + OFF_KV + 2112;
    float*    s_f2w = smem + OFF_W;          // reuses w region (dead after attnV)

    __shared__ int s_wide;

    const int b    = blockIdx.x;
    const int tid  = threadIdx.x;
    const int lane = tid & 31;
    const int warp = tid >> 5;

    // main GEMM: 4 m-warps x 2 n-warps, warp tile 32x64
    const int mw = warp & 3, nw = warp >> 2;
    const int m0 = mw * 32, n0 = nw * 64;

    const int q16 = tid & 15;
    const int cg  = tid >> 4;
    const int cq0 = cg * 8;

    uint32_t smem_u32;
    asm("{ .reg .u64 t; cvta.to.shared.u64 t, %1; cvt.u32.u64 %0, t; }"
        : "=r"(smem_u32) : "l"(smem));
    const uint32_t aBase  = smem_u32 + OFF_A * 4;
    const uint32_t bBase  = smem_u32 + OFF_B * 4;
    const uint32_t qwBase = smem_u32 + OFF_KV * 4;  // B(q) staging tile
    const uint32_t aL = aBase + (uint32_t)(m0 + (lane & 15)) * 528u + (uint32_t)(lane >> 4) * 16u;
    const uint32_t bL = bBase + (uint32_t)(n0 + (lane & 7) + ((lane & 16) >> 1)) * 528u
                              + (uint32_t)((lane >> 3) & 1) * 16u;
    // small q GEMM addressing: A rows 0..15, B(q) cols warp*16..+15
    const uint32_t aQ = aBase + (uint32_t)(lane & 15) * 528u + (uint32_t)(lane >> 4) * 16u;
    const uint32_t bQ = qwBase + (uint32_t)(warp * 16 + (lane & 7) + ((lane & 16) >> 1)) * 528u
                               + (uint32_t)((lane >> 3) & 1) * 16u;

    // ---- mask dtype probe ----
    if (tid == 0) s_wide = 1;
    __syncthreads();
    {
        const unsigned* mwp = reinterpret_cast<const unsigned*>(P.em);
        bool ok = true;
#pragma unroll
        for (int s = 0; s < 4; ++s) {
            unsigned w = __ldg(mwp + tid + 256 * s);
            ok = ok && (w == 0u || w == 1u || w == 0x3F800000u);
        }
        if (!ok) atomicAnd(&s_wide, 0);
    }
    __syncthreads();
    const bool wide = (s_wide != 0);

    if (tid < NEN) {
        bool m;
        if (wide) m = __ldg(reinterpret_cast<const unsigned*>(P.em) + (size_t)b * NEN + tid) != 0u;
        else      m = __ldg(P.em + (size_t)b * NEN + tid) != 0;
        s_emf[tid] = m ? 1.0f : 0.0f;
    }
    __syncthreads();
    if (tid == 0) {
        bool all = true;
#pragma unroll
        for (int i = 0; i < NEN; ++i) all = all && (s_emf[i] > 0.5f);
        s_flag[0] = all ? 1.0f : 0.0f;
    }
    __syncthreads();

    float acc[2][8][4];

    for (int p = 0; p < 2; ++p) {
        const float* fc1b = P.w[p * 7 + 1];
        const float* outw = P.w[p * 7 + 3];
        const float* outb = P.w[p * 7 + 4];
        const float* fc2w = P.w[p * 7 + 5];
        const float* fc2b = P.w[p * 7 + 6];
        const uint32_t* wt = g_wt + (p * 4) * TILE_U32;

        // ---- 1. (p=0 only) cp.async B(fc1); fill A (ent hi|lo) ----
        if (p == 0) copyB_async(bBase, wt, tid);
        {
            const float2* eg = reinterpret_cast<const float2*>(P.ents + (size_t)b * NEN * ED);
            for (int i = tid; i < NEN * (ED / 2); i += 256) {
                int e = i / (ED / 2), d2 = i % (ED / 2);
                float2 v = __ldg(eg + i);
                uint32_t hi, lo;
                split2(v.x, v.y, hi, lo);
                Au[e * STRB + d2]            = hi;
                Au[e * STRB + (ED / 2) + d2] = lo;
            }
        }
        if (p == 0) CP_WAIT0();   // p=1: fc1 tile was prefetched + waited in p=0 tail
        __syncthreads();

        // ---- 2. fc1 GEMM ----
        gemm_mma<ED>(aL, bL, acc);
        __syncthreads();

        // ---- 3. cp.async B(q)->staging, B(k)->B  +  x1 epilogue into A ----
        copyB_async(qwBase, wt + TILE_U32, tid);
        copyB_async(bBase,  wt + 2 * TILE_U32, tid);
#pragma unroll
        for (int mi = 0; mi < 2; ++mi)
#pragma unroll
            for (int nj2 = 0; nj2 < 8; ++nj2) {
                int r = m0 + mi * 16 + (lane >> 2);
                int c = n0 + nj2 * 8 + 2 * (lane & 3);
                float bias0 = __ldg(fc1b + c), bias1 = __ldg(fc1b + c + 1);
                float x0 = fmaxf(acc[mi][nj2][0] + bias0, 0.f);
                float x1v = fmaxf(acc[mi][nj2][1] + bias1, 0.f);
                uint32_t hi, lo;
                split2(x0, x1v, hi, lo);
                Au[r * STRB + (c >> 1)]      = hi;
                Au[r * STRB + 64 + (c >> 1)] = lo;
                x0  = fmaxf(acc[mi][nj2][2] + bias0, 0.f);
                x1v = fmaxf(acc[mi][nj2][3] + bias1, 0.f);
                split2(x0, x1v, hi, lo);
                Au[(r + 8) * STRB + (c >> 1)]      = hi;
                Au[(r + 8) * STRB + 64 + (c >> 1)] = lo;
            }
        CP_WAIT0();
        __syncthreads();

        // ---- 4. small q GEMM (M=16; each warp: 16x16 tile) + k GEMM ----
        {
            float qacc[2][4];
#pragma unroll
            for (int j = 0; j < 2; ++j)
#pragma unroll
                for (int r = 0; r < 4; ++r) qacc[j][r] = 0.f;
#pragma unroll
            for (int pass = 0; pass < 3; ++pass) {
                const uint32_t aO = (pass == 2) ? 256u : 0u;
                const uint32_t bO = (pass == 1) ? 256u : 0u;
#pragma unroll
                for (int kb = 0; kb < 256; kb += 32) {
                    uint32_t a[4], bbq[4];
                    ldmat4(a, aQ + aO + kb);
                    ldmat4(bbq, bQ + bO + kb);
                    mma16816(qacc[0], a, bbq[0], bbq[1]);
                    mma16816(qacc[1], a, bbq[2], bbq[3]);
                }
            }
            const float qs = 0.17677669529663687f;  // 1/sqrt(32)
            const int r = lane >> 2;
            const int cb = warp * 16 + 2 * (lane & 3);
#pragma unroll
            for (int nb = 0; nb < 2; ++nb) {
                const int c = cb + nb * 8;
                s_q[r * TSTRIDE + c]           = qacc[nb][0] * qs;
                s_q[r * TSTRIDE + c + 1]       = qacc[nb][1] * qs;
                s_q[(r + 8) * TSTRIDE + c]     = qacc[nb][2] * qs;
                s_q[(r + 8) * TSTRIDE + c + 1] = qacc[nb][3] * qs;
            }
        }
        gemm_mma<HE>(aL, bL, acc);   // k GEMM
        __syncthreads();

        // ---- 5. cp.async B(v) overlapped with kT writes + logits ----
        copyB_async(bBase, wt + 3 * TILE_U32, tid);
#pragma unroll
        for (int ph = 0; ph < 2; ++ph) {
            if (nw == ph) {
#pragma unroll
                for (int mi = 0; mi < 2; ++mi)
#pragma unroll
                    for (int nj2 = 0; nj2 < 8; ++nj2) {
                        int ent = m0 + mi * 16 + (lane >> 2);
                        int f = nj2 * 8 + 2 * (lane & 3);
                        s_kv[f * TSTRIDE + ent]           = acc[mi][nj2][0];
                        s_kv[(f + 1) * TSTRIDE + ent]     = acc[mi][nj2][1];
                        s_kv[f * TSTRIDE + ent + 8]       = acc[mi][nj2][2];
                        s_kv[(f + 1) * TSTRIDE + ent + 8] = acc[mi][nj2][3];
                    }
            }
            __syncthreads();
            {
                const int hl = warp >> 2;
                const int h  = ph * 2 + hl;
                const int e  = (warp & 3) * 32 + lane;
                float2 kvv[16];
#pragma unroll
                for (int d2 = 0; d2 < 16; ++d2) {
                    kvv[d2].x = s_kv[(hl * 32 + 2 * d2 + 0) * TSTRIDE + e];
                    kvv[d2].y = s_kv[(hl * 32 + 2 * d2 + 1) * TSTRIDE + e];
                }
#pragma unroll 2
                for (int q = 0; q < 16; ++q) {
                    const float* qrow = s_q + q * TSTRIDE + h * 32;
                    float2 a0 = make_float2(0.f, 0.f), a1 = make_float2(0.f, 0.f);
#pragma unroll
                    for (int d4 = 0; d4 < 8; ++d4) {
                        float4 q4 = *reinterpret_cast<const float4*>(qrow + d4 * 4);
                        a0 = ffma2(make_float2(q4.x, q4.y), kvv[d4 * 2 + 0], a0);
                        a1 = ffma2(make_float2(q4.z, q4.w), kvv[d4 * 2 + 1], a1);
                    }
                    s_w[(h * 16 + q) * SWST + e] = a0.x + a0.y + a1.x + a1.y;
                }
            }
            __syncthreads();
        }

        // ---- 6. masked softmax ----
        for (int it = 0; it < 8; ++it) {
            int pair = warp * 8 + it;
            int q = pair & 15;
            bool qmask = s_emf[q] > 0.5f;
            float lg[4];
#pragma unroll
            for (int j = 0; j < 4; ++j) {
                int k = lane + 32 * j;
                lg[j] = (qmask || s_emf[k] > 0.5f) ? -1e9f : s_w[pair * SWST + k];
            }
            float mx = fmaxf(fmaxf(lg[0], lg[1]), fmaxf(lg[2], lg[3]));
#pragma unroll
            for (int o = 16; o > 0; o >>= 1)
                mx = fmaxf(mx, __shfl_xor_sync(0xffffffffu, mx, o));
            float e[4];
            float sum = 0.f;
#pragma unroll
            for (int j = 0; j < 4; ++j) { e[j] = __expf(lg[j] - mx); sum += e[j]; }
#pragma unroll
            for (int o = 16; o > 0; o >>= 1)
                sum += __shfl_xor_sync(0xffffffffu, sum, o);
            bool allm = qmask || (s_flag[0] > 0.5f);
            float inv = allm ? 0.f : 1.f / sum;
#pragma unroll
            for (int j = 0; j < 4; ++j)
                s_w[pair * SWST + lane + 32 * j] = e[j] * inv;
        }
        CP_WAIT0();
        __syncthreads();

        // ---- 7. v GEMM ----
        gemm_mma<HE>(aL, bL, acc);
        __syncthreads();

        // ---- 7b. (p=0) prefetch next pass's fc1 tile into B — hides under whole tail ----
        if (p == 0) copyB_async(bBase, g_wt + 4 * TILE_U32, tid);

        // ---- 8. two-phase vT write + attnV (attn -> q region; q dead) ----
#pragma unroll
        for (int ph = 0; ph < 2; ++ph) {
            if (nw == ph) {
#pragma unroll
                for (int mi = 0; mi < 2; ++mi)
#pragma unroll
                    for (int nj2 = 0; nj2 < 8; ++nj2) {
                        int ent = m0 + mi * 16 + (lane >> 2);
                        int f = nj2 * 8 + 2 * (lane & 3);
                        s_kv[f * TSTRIDE + ent]           = acc[mi][nj2][0];
                        s_kv[(f + 1) * TSTRIDE + ent]     = acc[mi][nj2][1];
                        s_kv[f * TSTRIDE + ent + 8]       = acc[mi][nj2][2];
                        s_kv[(f + 1) * TSTRIDE + ent + 8] = acc[mi][nj2][3];
                    }
            }
            __syncthreads();
            if ((cg >> 3) == ph) {
                const int h  = cq0 >> 5;
                const int lf = cq0 - ph * 64;
                float2 a2[8];
#pragma unroll
                for (int j = 0; j < 8; ++j) a2[j] = make_float2(0.f, 0.f);
                const float* wrow = s_w + (h * 16 + q16) * SWST;
#pragma unroll 4
                for (int e0 = 0; e0 < NEN; e0 += 4) {
                    float4 w4 = *reinterpret_cast<const float4*>(wrow + e0);
                    float2 wlo = make_float2(w4.x, w4.y);
                    float2 whi = make_float2(w4.z, w4.w);
#pragma unroll
                    for (int jc = 0; jc < 8; ++jc) {
                        float4 v4 = *reinterpret_cast<const float4*>(&s_kv[(lf + jc) * TSTRIDE + e0]);
                        a2[jc] = ffma2(wlo, make_float2(v4.x, v4.y), a2[jc]);
                        a2[jc] = ffma2(whi, make_float2(v4.z, v4.w), a2[jc]);
                    }
                }
                float* ar = s_attn + q16 * TSTRIDE + cq0;
                *reinterpret_cast<float4*>(ar) = make_float4(
                    a2[0].x + a2[0].y, a2[1].x + a2[1].y, a2[2].x + a2[2].y, a2[3].x + a2[3].y);
                *reinterpret_cast<float4*>(ar + 4) = make_float4(
                    a2[4].x + a2[4].y, a2[5].x + a2[5].y, a2[6].x + a2[6].y, a2[7].x + a2[7].y);
            }
            __syncthreads();
        }

        // ---- 9. cp.async fc2w -> w region (s_w dead) + out = attn @ out_w + out_b ----
        {
            const float4* fg = reinterpret_cast<const float4*>(fc2w);
#pragma unroll 1
            for (int i = tid; i < (HE * MD) / 4; i += 256)
                cp_async16(smem_u32 + (uint32_t)(OFF_W + i * 4) * 4u, fg + i);
            asm volatile("cp.async.commit_group;" ::: "memory");
        }
        {
            float2 acc2[4];
#pragma unroll
            for (int j = 0; j < 4; ++j) acc2[j] = make_float2(0.f, 0.f);
            const float* Bo = outw + cq0;
#pragma unroll 4
            for (int k0 = 0; k0 < HE; k0 += 4) {
                float4 a4 = *reinterpret_cast<const float4*>(&s_attn[q16 * TSTRIDE + k0]);
                float av[4] = {a4.x, a4.y, a4.z, a4.w};
#pragma unroll
                for (int t = 0; t < 4; ++t) {
                    const float4* bp = reinterpret_cast<const float4*>(Bo + (k0 + t) * HE);
                    float4 b0 = __ldg(bp);
                    float4 b1 = __ldg(bp + 1);
                    float2 aa = make_float2(av[t], av[t]);
                    acc2[0] = ffma2(aa, make_float2(b0.x, b0.y), acc2[0]);
                    acc2[1] = ffma2(aa, make_float2(b0.z, b0.w), acc2[1]);
                    acc2[2] = ffma2(aa, make_float2(b1.x, b1.y), acc2[2]);
                    acc2[3] = ffma2(aa, make_float2(b1.z, b1.w), acc2[3]);
                }
            }
            float maskv = (s_emf[q16] > 0.5f) ? 0.f : 1.f;
            float4 ob0 = *reinterpret_cast<const float4*>(outb + cq0);
            float4 ob1 = *reinterpret_cast<const float4*>(outb + cq0 + 4);
            // s_out (kv region) is disjoint from s_attn (q region): no barrier needed here
            float* orow = s_out + q16 * TSTRIDE + cq0;
            *reinterpret_cast<float4*>(orow) = make_float4(
                (acc2[0].x + ob0.x) * maskv, (acc2[0].y + ob0.y) * maskv,
                (acc2[1].x + ob0.z) * maskv, (acc2[1].y + ob0.w) * maskv);
            *reinterpret_cast<float4*>(orow + 4) = make_float4(
                (acc2[2].x + ob1.x) * maskv, (acc2[2].y + ob1.y) * maskv,
                (acc2[3].x + ob1.z) * maskv, (acc2[3].y + ob1.w) * maskv);
        }
        CP_WAIT0();      // fc2w staged (and p=1 fc1 prefetch complete)
        __syncthreads();

        // ---- 10. x3 = out @ fc2_w + fc2_b, masked (fc2w from smem) ----
        {
            const int m0x = cg * 2;
            float2 acc2 = make_float2(0.f, 0.f);
#pragma unroll 8
            for (int k0 = 0; k0 < HE; k0 += 4) {
                float4 a4 = *reinterpret_cast<const float4*>(&s_out[q16 * TSTRIDE + k0]);
                float av[4] = {a4.x, a4.y, a4.z, a4.w};
#pragma unroll
                for (int t = 0; t < 4; ++t) {
                    float2 bw = *reinterpret_cast<const float2*>(&s_f2w[(k0 + t) * MD + m0x]);
                    acc2 = ffma2(make_float2(av[t], av[t]), bw, acc2);
                }
            }
            float maskv = (s_emf[q16] > 0.5f) ? 0.f : 1.f;
            s_x3[q16 * MD + m0x]     = (acc2.x + fc2b[m0x])     * maskv;
            s_x3[q16 * MD + m0x + 1] = (acc2.y + fc2b[m0x + 1]) * maskv;
        }
        __syncthreads();

        if (tid < NA) {
            float s = 0.f;
#pragma unroll
            for (int m = 0; m < MD; ++m) s += s_x3[tid * MD + m];
            float rm = s * (1.f / MD);
            s_rm[tid] = rm;
            if (p == 0) s_w1m[tid] = rm;
        }
        __syncthreads();
    }

    if (tid == 0) {
        float vm = 0.f;
#pragma unroll
        for (int q = 0; q < NA; ++q) vm += s_rm[q];
        vm *= (1.f / NA);
        const float* qb = P.qs + (size_t)b * NA;
        float qt = 0.f;
#pragma unroll
        for (int a = 0; a < NA; ++a) qt += qb[a] * fabsf(s_w1m[a]);
        P.out[b] = qt + vm;
    }
}

extern "C" void kernel_launch(void* const* d_in, const int* in_sizes, int n_in,
                              void* d_out, int out_size) {
    KParams P;
    P.qs   = (const float*)d_in[0];
    P.ents = (const float*)d_in[1];
    P.em   = (const unsigned char*)d_in[2];
    for (int i = 0; i < 14; ++i) P.w[i] = (const float*)d_in[3 + i];
    P.out = (float*)d_out;

    cudaFuncSetAttribute(mixer_kernel, cudaFuncAttributeMaxDynamicSharedMemorySize, SMEM_BYTES);

    dim3 pgrid((128 * 16 + 255) / 256, 8);
    prep_kernel<<<pgrid, 256>>>(P);

    int nb = in_sizes[0] / NA;  // 1600
    mixer_kernel<<<nb, 256, SMEM_BYTES>>>(P);
}

// round 14
// speedup vs baseline: 1.0748x; 1.0748x over previous
#include <cuda_runtime.h>
#include <cuda_bf16.h>
#include <cstdint>

#define NA 16
#define NEN 128
#define ED 96
#define HE 128
#define MD 32
#define NH 4
#define HD 32
#define TSTRIDE 132   // fp32 stride (528B)
#define STRB 132      // u32 stride of bf16 tiles (528B)
#define SWST 132

// ---- smem float offsets ----
#define OFF_A    0        // A tile: 128 x 264 bf16 = 67584B
#define OFF_B    16896    // B tile: same (dead after v GEMM -> outw fp32 staging)
#define OFF_KV   33792    // 64 x 132 fp32 kT/vT (+ B(q) staging early); after attnV: s_out + s_x3
#define OFF_W    42240    // 64 x 132 softmax w; after attnV: fc2w staging (4096 fp32)
#define OFF_Q    50688    // 16 x 132 q; after logits: s_attn
#define OFF_EMF  52800
#define OFF_RM   52928
#define OFF_W1   52944
#define OFF_FLAG 52960
#define SMEM_FLOATS 52968
#define SMEM_BYTES (SMEM_FLOATS * 4)

#define TILE_U32 (128 * 132)

struct KParams {
    const float* qs;
    const float* ents;
    const unsigned char* em;
    const float* w[14];
    float* out;
};

__device__ uint32_t g_wt[8 * TILE_U32];

static __device__ __forceinline__ void split2(float a, float b, uint32_t& hi, uint32_t& lo) {
    __nv_bfloat16 ha = __float2bfloat16(a), hb = __float2bfloat16(b);
    float ra = a - __bfloat162float(ha), rb = b - __bfloat162float(hb);
    __nv_bfloat16 la = __float2bfloat16(ra), lb = __float2bfloat16(rb);
    hi = (uint32_t)__bfloat16_as_ushort(ha) | ((uint32_t)__bfloat16_as_ushort(hb) << 16);
    lo = (uint32_t)__bfloat16_as_ushort(la) | ((uint32_t)__bfloat16_as_ushort(lb) << 16);
}

static __device__ __forceinline__ float2 ffma2(float2 a, float2 b, float2 c) {
    unsigned long long au = *reinterpret_cast<unsigned long long*>(&a);
    unsigned long long bu = *reinterpret_cast<unsigned long long*>(&b);
    unsigned long long cu = *reinterpret_cast<unsigned long long*>(&c);
    asm("fma.rn.f32x2 %0, %1, %2, %0;" : "+l"(cu) : "l"(au), "l"(bu));
    return *reinterpret_cast<float2*>(&cu);
}

static __device__ __forceinline__ void ldmat4(uint32_t (&r)[4], uint32_t addr) {
    asm volatile("ldmatrix.sync.aligned.m8n8.x4.shared.b16 {%0,%1,%2,%3}, [%4];"
        : "=r"(r[0]), "=r"(r[1]), "=r"(r[2]), "=r"(r[3]) : "r"(addr));
}

static __device__ __forceinline__ void mma16816(float (&d)[4], const uint32_t (&a)[4],
                                                uint32_t b0, uint32_t b1) {
    asm volatile("mma.sync.aligned.m16n8k16.row.col.f32.bf16.bf16.f32 "
        "{%0,%1,%2,%3}, {%4,%5,%6,%7}, {%8,%9}, {%0,%1,%2,%3};"
        : "+f"(d[0]), "+f"(d[1]), "+f"(d[2]), "+f"(d[3])
        : "r"(a[0]), "r"(a[1]), "r"(a[2]), "r"(a[3]), "r"(b0), "r"(b1));
}

static __device__ __forceinline__ void cp_async16(uint32_t saddr, const void* g) {
    asm volatile("cp.async.cg.shared.global [%0], [%1], 16;" :: "r"(saddr), "l"(g));
}

static __device__ __forceinline__ void copyB_async(uint32_t base, const uint32_t* g, int tid) {
#pragma unroll 1
    for (int i = tid; i < TILE_U32 / 4; i += 256)
        cp_async16(base + (uint32_t)i * 16u, g + i * 4);
    asm volatile("cp.async.commit_group;" ::: "memory");
}
#define CP_WAIT0() asm volatile("cp.async.wait_group 0;" ::: "memory")
#define CP_WAIT1() asm volatile("cp.async.wait_group 1;" ::: "memory")

// Split-3 bf16 GEMM, warp tile 32x64.
template<int K>
static __device__ __forceinline__ void gemm_mma(uint32_t aL, uint32_t bL, float (&acc)[2][8][4]) {
#pragma unroll
    for (int i = 0; i < 2; ++i)
#pragma unroll
        for (int j = 0; j < 8; ++j)
#pragma unroll
            for (int r = 0; r < 4; ++r) acc[i][j][r] = 0.f;
#pragma unroll
    for (int pass = 0; pass < 3; ++pass) {
        const uint32_t aO = (pass == 2) ? (uint32_t)(K * 2) : 0u;
        const uint32_t bO = (pass == 1) ? (uint32_t)(K * 2) : 0u;
#pragma unroll
        for (int kb = 0; kb < K * 2; kb += 32) {
            uint32_t a[2][4], bb[4][4];
            ldmat4(a[0], aL + aO + kb);
            ldmat4(a[1], aL + 16u * 528u + aO + kb);
#pragma unroll
            for (int nj = 0; nj < 4; ++nj)
                ldmat4(bb[nj], bL + (uint32_t)nj * 16u * 528u + bO + kb);
#pragma unroll
            for (int mi = 0; mi < 2; ++mi)
#pragma unroll
                for (int nj = 0; nj < 4; ++nj) {
                    mma16816(acc[mi][2 * nj],     a[mi], bb[nj][0], bb[nj][1]);
                    mma16816(acc[mi][2 * nj + 1], a[mi], bb[nj][2], bb[nj][3]);
                }
        }
    }
}

// ---- prep kernel: split weights into tile-image layout ----
__global__ void prep_kernel(KParams P) {
    const int t = blockIdx.y;
    const int p = t >> 2, ch = t & 3;
    const float* W; int ldb, KP;
    if (ch == 0) { W = P.w[p * 7 + 0]; ldb = HE;     KP = ED / 2; }
    else         { W = P.w[p * 7 + 2] + (ch - 1) * HE; ldb = 3 * HE; KP = 64; }
    uint32_t* dst = g_wt + t * TILE_U32;
    const int nkpb = KP >> 2;
    int idx = blockIdx.x * blockDim.x + threadIdx.x;
    if (idx >= 128 * nkpb) return;
    int n = idx / nkpb, kpb = idx % nkpb;
    uint32_t hi[4], lo[4];
#pragma unroll
    for (int j = 0; j < 4; ++j) {
        int kp = kpb * 4 + j;
        float w0 = __ldg(W + (size_t)(2 * kp) * ldb + n);
        float w1 = __ldg(W + (size_t)(2 * kp + 1) * ldb + n);
        split2(w0, w1, hi[j], lo[j]);
    }
    *reinterpret_cast<uint4*>(dst + n * STRB + kpb * 4)      = make_uint4(hi[0], hi[1], hi[2], hi[3]);
    *reinterpret_cast<uint4*>(dst + n * STRB + KP + kpb * 4) = make_uint4(lo[0], lo[1], lo[2], lo[3]);
}

__global__ void __launch_bounds__(256, 1)
mixer_kernel(KParams P) {
    extern __shared__ float smem[];
    uint32_t* Au    = reinterpret_cast<uint32_t*>(smem + OFF_A);
    float*    s_kv  = smem + OFF_KV;
    float*    s_w   = smem + OFF_W;
    float*    s_q   = smem + OFF_Q;
    float*    s_emf = smem + OFF_EMF;
    float*    s_rm  = smem + OFF_RM;
    float*    s_w1m = smem + OFF_W1;
    float*    s_flag= smem + OFF_FLAG;
    float*    s_attn= smem + OFF_Q;          // reuses q region (dead after logits)
    float*    s_out = smem + OFF_KV;         // reuses kv region (dead after attnV)
    float*    s_x3  = smem + OFF_KV + 2112;
    float*    s_f2w = smem + OFF_W;          // reuses w region (dead after attnV)
    float*    s_ow  = smem + OFF_B;          // outw fp32 staging (B dead after v GEMM)

    __shared__ int s_wide;

    const int b    = blockIdx.x;
    const int tid  = threadIdx.x;
    const int lane = tid & 31;
    const int warp = tid >> 5;

    // main GEMM: 4 m-warps x 2 n-warps, warp tile 32x64
    const int mw = warp & 3, nw = warp >> 2;
    const int m0 = mw * 32, n0 = nw * 64;

    const int q16 = tid & 15;
    const int cg  = tid >> 4;
    const int cq0 = cg * 8;

    uint32_t smem_u32;
    asm("{ .reg .u64 t; cvta.to.shared.u64 t, %1; cvt.u32.u64 %0, t; }"
        : "=r"(smem_u32) : "l"(smem));
    const uint32_t aBase  = smem_u32 + OFF_A * 4;
    const uint32_t bBase  = smem_u32 + OFF_B * 4;
    const uint32_t qwBase = smem_u32 + OFF_KV * 4;  // B(q) staging tile
    const uint32_t aL = aBase + (uint32_t)(m0 + (lane & 15)) * 528u + (uint32_t)(lane >> 4) * 16u;
    const uint32_t bL = bBase + (uint32_t)(n0 + (lane & 7) + ((lane & 16) >> 1)) * 528u
                              + (uint32_t)((lane >> 3) & 1) * 16u;
    // small q GEMM addressing: A rows 0..15, B(q) cols warp*16..+15
    const uint32_t aQ = aBase + (uint32_t)(lane & 15) * 528u + (uint32_t)(lane >> 4) * 16u;
    const uint32_t bQ = qwBase + (uint32_t)(warp * 16 + (lane & 7) + ((lane & 16) >> 1)) * 528u
                               + (uint32_t)((lane >> 3) & 1) * 16u;

    // ---- mask dtype probe ----
    if (tid == 0) s_wide = 1;
    __syncthreads();
    {
        const unsigned* mwp = reinterpret_cast<const unsigned*>(P.em);
        bool ok = true;
#pragma unroll
        for (int s = 0; s < 4; ++s) {
            unsigned w = __ldg(mwp + tid + 256 * s);
            ok = ok && (w == 0u || w == 1u || w == 0x3F800000u);
        }
        if (!ok) atomicAnd(&s_wide, 0);
    }
    __syncthreads();
    const bool wide = (s_wide != 0);

    if (tid < NEN) {
        bool m;
        if (wide) m = __ldg(reinterpret_cast<const unsigned*>(P.em) + (size_t)b * NEN + tid) != 0u;
        else      m = __ldg(P.em + (size_t)b * NEN + tid) != 0;
        s_emf[tid] = m ? 1.0f : 0.0f;
    }
    __syncthreads();
    if (tid == 0) {
        bool all = true;
#pragma unroll
        for (int i = 0; i < NEN; ++i) all = all && (s_emf[i] > 0.5f);
        s_flag[0] = all ? 1.0f : 0.0f;
    }
    __syncthreads();

    float acc[2][8][4];

    for (int p = 0; p < 2; ++p) {
        const float* fc1b = P.w[p * 7 + 1];
        const float* outw = P.w[p * 7 + 3];
        const float* outb = P.w[p * 7 + 4];
        const float* fc2w = P.w[p * 7 + 5];
        const float* fc2b = P.w[p * 7 + 6];
        const uint32_t* wt = g_wt + (p * 4) * TILE_U32;

        // ---- 1. cp.async B(fc1) + fill A (ent hi|lo) ----
        copyB_async(bBase, wt, tid);
        {
            const float2* eg = reinterpret_cast<const float2*>(P.ents + (size_t)b * NEN * ED);
            for (int i = tid; i < NEN * (ED / 2); i += 256) {
                int e = i / (ED / 2), d2 = i % (ED / 2);
                float2 v = __ldg(eg + i);
                uint32_t hi, lo;
                split2(v.x, v.y, hi, lo);
                Au[e * STRB + d2]            = hi;
                Au[e * STRB + (ED / 2) + d2] = lo;
            }
        }
        CP_WAIT0();
        __syncthreads();

        // ---- 2. fc1 GEMM ----
        gemm_mma<ED>(aL, bL, acc);
        __syncthreads();

        // ---- 3. cp.async B(q)->staging, B(k)->B  +  x1 epilogue into A ----
        copyB_async(qwBase, wt + TILE_U32, tid);
        copyB_async(bBase,  wt + 2 * TILE_U32, tid);
#pragma unroll
        for (int mi = 0; mi < 2; ++mi)
#pragma unroll
            for (int nj2 = 0; nj2 < 8; ++nj2) {
                int r = m0 + mi * 16 + (lane >> 2);
                int c = n0 + nj2 * 8 + 2 * (lane & 3);
                float bias0 = __ldg(fc1b + c), bias1 = __ldg(fc1b + c + 1);
                float x0 = fmaxf(acc[mi][nj2][0] + bias0, 0.f);
                float x1v = fmaxf(acc[mi][nj2][1] + bias1, 0.f);
                uint32_t hi, lo;
                split2(x0, x1v, hi, lo);
                Au[r * STRB + (c >> 1)]      = hi;
                Au[r * STRB + 64 + (c >> 1)] = lo;
                x0  = fmaxf(acc[mi][nj2][2] + bias0, 0.f);
                x1v = fmaxf(acc[mi][nj2][3] + bias1, 0.f);
                split2(x0, x1v, hi, lo);
                Au[(r + 8) * STRB + (c >> 1)]      = hi;
                Au[(r + 8) * STRB + 64 + (c >> 1)] = lo;
            }
        CP_WAIT0();
        __syncthreads();

        // ---- 4. small q GEMM (M=16; each warp: 16x16 tile) + k GEMM ----
        {
            float qacc[2][4];
#pragma unroll
            for (int j = 0; j < 2; ++j)
#pragma unroll
                for (int r = 0; r < 4; ++r) qacc[j][r] = 0.f;
#pragma unroll
            for (int pass = 0; pass < 3; ++pass) {
                const uint32_t aO = (pass == 2) ? 256u : 0u;
                const uint32_t bO = (pass == 1) ? 256u : 0u;
#pragma unroll
                for (int kb = 0; kb < 256; kb += 32) {
                    uint32_t a[4], bbq[4];
                    ldmat4(a, aQ + aO + kb);
                    ldmat4(bbq, bQ + bO + kb);
                    mma16816(qacc[0], a, bbq[0], bbq[1]);
                    mma16816(qacc[1], a, bbq[2], bbq[3]);
                }
            }
            const float qs = 0.17677669529663687f;  // 1/sqrt(32)
            const int r = lane >> 2;
            const int cb = warp * 16 + 2 * (lane & 3);
#pragma unroll
            for (int nb = 0; nb < 2; ++nb) {
                const int c = cb + nb * 8;
                s_q[r * TSTRIDE + c]           = qacc[nb][0] * qs;
                s_q[r * TSTRIDE + c + 1]       = qacc[nb][1] * qs;
                s_q[(r + 8) * TSTRIDE + c]     = qacc[nb][2] * qs;
                s_q[(r + 8) * TSTRIDE + c + 1] = qacc[nb][3] * qs;
            }
        }
        gemm_mma<HE>(aL, bL, acc);   // k GEMM
        __syncthreads();

        // ---- 5. cp.async B(v) overlapped with kT writes + logits ----
        copyB_async(bBase, wt + 3 * TILE_U32, tid);
#pragma unroll
        for (int ph = 0; ph < 2; ++ph) {
            if (nw == ph) {
#pragma unroll
                for (int mi = 0; mi < 2; ++mi)
#pragma unroll
                    for (int nj2 = 0; nj2 < 8; ++nj2) {
                        int ent = m0 + mi * 16 + (lane >> 2);
                        int f = nj2 * 8 + 2 * (lane & 3);
                        s_kv[f * TSTRIDE + ent]           = acc[mi][nj2][0];
                        s_kv[(f + 1) * TSTRIDE + ent]     = acc[mi][nj2][1];
                        s_kv[f * TSTRIDE + ent + 8]       = acc[mi][nj2][2];
                        s_kv[(f + 1) * TSTRIDE + ent + 8] = acc[mi][nj2][3];
                    }
            }
            __syncthreads();
            {
                const int hl = warp >> 2;
                const int h  = ph * 2 + hl;
                const int e  = (warp & 3) * 32 + lane;
                float2 kvv[16];
#pragma unroll
                for (int d2 = 0; d2 < 16; ++d2) {
                    kvv[d2].x = s_kv[(hl * 32 + 2 * d2 + 0) * TSTRIDE + e];
                    kvv[d2].y = s_kv[(hl * 32 + 2 * d2 + 1) * TSTRIDE + e];
                }
#pragma unroll 2
                for (int q = 0; q < 16; ++q) {
                    const float* qrow = s_q + q * TSTRIDE + h * 32;
                    float2 a0 = make_float2(0.f, 0.f), a1 = make_float2(0.f, 0.f);
#pragma unroll
                    for (int d4 = 0; d4 < 8; ++d4) {
                        float4 q4 = *reinterpret_cast<const float4*>(qrow + d4 * 4);
                        a0 = ffma2(make_float2(q4.x, q4.y), kvv[d4 * 2 + 0], a0);
                        a1 = ffma2(make_float2(q4.z, q4.w), kvv[d4 * 2 + 1], a1);
                    }
                    s_w[(h * 16 + q) * SWST + e] = a0.x + a0.y + a1.x + a1.y;
                }
            }
            __syncthreads();
        }

        // ---- 6. masked softmax ----
        for (int it = 0; it < 8; ++it) {
            int pair = warp * 8 + it;
            int q = pair & 15;
            bool qmask = s_emf[q] > 0.5f;
            float lg[4];
#pragma unroll
            for (int j = 0; j < 4; ++j) {
                int k = lane + 32 * j;
                lg[j] = (qmask || s_emf[k] > 0.5f) ? -1e9f : s_w[pair * SWST + k];
            }
            float mx = fmaxf(fmaxf(lg[0], lg[1]), fmaxf(lg[2], lg[3]));
#pragma unroll
            for (int o = 16; o > 0; o >>= 1)
                mx = fmaxf(mx, __shfl_xor_sync(0xffffffffu, mx, o));
            float e[4];
            float sum = 0.f;
#pragma unroll
            for (int j = 0; j < 4; ++j) { e[j] = __expf(lg[j] - mx); sum += e[j]; }
#pragma unroll
            for (int o = 16; o > 0; o >>= 1)
                sum += __shfl_xor_sync(0xffffffffu, sum, o);
            bool allm = qmask || (s_flag[0] > 0.5f);
            float inv = allm ? 0.f : 1.f / sum;
#pragma unroll
            for (int j = 0; j < 4; ++j)
                s_w[pair * SWST + lane + 32 * j] = e[j] * inv;
        }
        CP_WAIT0();
        __syncthreads();

        // ---- 7. v GEMM ----
        gemm_mma<HE>(aL, bL, acc);
        __syncthreads();

        // ---- 7b. cp.async outw (fp32, 64KB) into dead B region — hides under attnV ----
        {
            const float4* og = reinterpret_cast<const float4*>(outw);
#pragma unroll 1
            for (int i = tid; i < (HE * HE) / 4; i += 256)
                cp_async16(bBase + (uint32_t)i * 16u, og + i);
            asm volatile("cp.async.commit_group;" ::: "memory");
        }

        // ---- 8. two-phase vT write + attnV (attn -> q region; q dead) ----
#pragma unroll
        for (int ph = 0; ph < 2; ++ph) {
            if (nw == ph) {
#pragma unroll
                for (int mi = 0; mi < 2; ++mi)
#pragma unroll
                    for (int nj2 = 0; nj2 < 8; ++nj2) {
                        int ent = m0 + mi * 16 + (lane >> 2);
                        int f = nj2 * 8 + 2 * (lane & 3);
                        s_kv[f * TSTRIDE + ent]           = acc[mi][nj2][0];
                        s_kv[(f + 1) * TSTRIDE + ent]     = acc[mi][nj2][1];
                        s_kv[f * TSTRIDE + ent + 8]       = acc[mi][nj2][2];
                        s_kv[(f + 1) * TSTRIDE + ent + 8] = acc[mi][nj2][3];
                    }
            }
            __syncthreads();
            if ((cg >> 3) == ph) {
                const int h  = cq0 >> 5;
                const int lf = cq0 - ph * 64;
                float2 a2[8];
#pragma unroll
                for (int j = 0; j < 8; ++j) a2[j] = make_float2(0.f, 0.f);
                const float* wrow = s_w + (h * 16 + q16) * SWST;
#pragma unroll 4
                for (int e0 = 0; e0 < NEN; e0 += 4) {
                    float4 w4 = *reinterpret_cast<const float4*>(wrow + e0);
                    float2 wlo = make_float2(w4.x, w4.y);
                    float2 whi = make_float2(w4.z, w4.w);
#pragma unroll
                    for (int jc = 0; jc < 8; ++jc) {
                        float4 v4 = *reinterpret_cast<const float4*>(&s_kv[(lf + jc) * TSTRIDE + e0]);
                        a2[jc] = ffma2(wlo, make_float2(v4.x, v4.y), a2[jc]);
                        a2[jc] = ffma2(whi, make_float2(v4.z, v4.w), a2[jc]);
                    }
                }
                float* ar = s_attn + q16 * TSTRIDE + cq0;
                *reinterpret_cast<float4*>(ar) = make_float4(
                    a2[0].x + a2[0].y, a2[1].x + a2[1].y, a2[2].x + a2[2].y, a2[3].x + a2[3].y);
                *reinterpret_cast<float4*>(ar + 4) = make_float4(
                    a2[4].x + a2[4].y, a2[5].x + a2[5].y, a2[6].x + a2[6].y, a2[7].x + a2[7].y);
            }
            __syncthreads();
        }

        // ---- 9. cp.async fc2w -> w region (s_w dead); wait outw; out-projection from smem ----
        {
            const float4* fg = reinterpret_cast<const float4*>(fc2w);
#pragma unroll 1
            for (int i = tid; i < (HE * MD) / 4; i += 256)
                cp_async16(smem_u32 + (uint32_t)(OFF_W + i * 4) * 4u, fg + i);
            asm volatile("cp.async.commit_group;" ::: "memory");
        }
        CP_WAIT1();       // outw staged
        __syncthreads();  // publish outw to all threads
        {
            float2 acc2[4];
#pragma unroll
            for (int j = 0; j < 4; ++j) acc2[j] = make_float2(0.f, 0.f);
            const float* Bo = s_ow + cq0;
#pragma unroll 4
            for (int k0 = 0; k0 < HE; k0 += 4) {
                float4 a4 = *reinterpret_cast<const float4*>(&s_attn[q16 * TSTRIDE + k0]);
                float av[4] = {a4.x, a4.y, a4.z, a4.w};
#pragma unroll
                for (int t = 0; t < 4; ++t) {
                    float4 b0 = *reinterpret_cast<const float4*>(Bo + (k0 + t) * HE);
                    float4 b1 = *reinterpret_cast<const float4*>(Bo + (k0 + t) * HE + 4);
                    float2 aa = make_float2(av[t], av[t]);
                    acc2[0] = ffma2(aa, make_float2(b0.x, b0.y), acc2[0]);
                    acc2[1] = ffma2(aa, make_float2(b0.z, b0.w), acc2[1]);
                    acc2[2] = ffma2(aa, make_float2(b1.x, b1.y), acc2[2]);
                    acc2[3] = ffma2(aa, make_float2(b1.z, b1.w), acc2[3]);
                }
            }
            float maskv = (s_emf[q16] > 0.5f) ? 0.f : 1.f;
            float4 ob0 = *reinterpret_cast<const float4*>(outb + cq0);
            float4 ob1 = *reinterpret_cast<const float4*>(outb + cq0 + 4);
            // s_out (kv region) disjoint from s_attn (q region): no extra barrier
            float* orow = s_out + q16 * TSTRIDE + cq0;
            *reinterpret_cast<float4*>(orow) = make_float4(
                (acc2[0].x + ob0.x) * maskv, (acc2[0].y + ob0.y) * maskv,
                (acc2[1].x + ob0.z) * maskv, (acc2[1].y + ob0.w) * maskv);
            *reinterpret_cast<float4*>(orow + 4) = make_float4(
                (acc2[2].x + ob1.x) * maskv, (acc2[2].y + ob1.y) * maskv,
                (acc2[3].x + ob1.z) * maskv, (acc2[3].y + ob1.w) * maskv);
        }
        CP_WAIT0();      // fc2w staged
        __syncthreads();

        // ---- 10. x3 = out @ fc2_w + fc2_b, masked (fc2w from smem) ----
        {
            const int m0x = cg * 2;
            float2 acc2 = make_float2(0.f, 0.f);
#pragma unroll 8
            for (int k0 = 0; k0 < HE; k0 += 4) {
                float4 a4 = *reinterpret_cast<const float4*>(&s_out[q16 * TSTRIDE + k0]);
                float av[4] = {a4.x, a4.y, a4.z, a4.w};
#pragma unroll
                for (int t = 0; t < 4; ++t) {
                    float2 bw = *reinterpret_cast<const float2*>(&s_f2w[(k0 + t) * MD + m0x]);
                    acc2 = ffma2(make_float2(av[t], av[t]), bw, acc2);
                }
            }
            float maskv = (s_emf[q16] > 0.5f) ? 0.f : 1.f;
            s_x3[q16 * MD + m0x]     = (acc2.x + fc2b[m0x])     * maskv;
            s_x3[q16 * MD + m0x + 1] = (acc2.y + fc2b[m0x + 1]) * maskv;
        }
        __syncthreads();

        if (tid < NA) {
            float s = 0.f;
#pragma unroll
            for (int m = 0; m < MD; ++m) s += s_x3[tid * MD + m];
            float rm = s * (1.f / MD);
            s_rm[tid] = rm;
            if (p == 0) s_w1m[tid] = rm;
        }
        __syncthreads();
    }

    if (tid == 0) {
        float vm = 0.f;
#pragma unroll
        for (int q = 0; q < NA; ++q) vm += s_rm[q];
        vm *= (1.f / NA);
        const float* qb = P.qs + (size_t)b * NA;
        float qt = 0.f;
#pragma unroll
        for (int a = 0; a < NA; ++a) qt += qb[a] * fabsf(s_w1m[a]);
        P.out[b] = qt + vm;
    }
}

extern "C" void kernel_launch(void* const* d_in, const int* in_sizes, int n_in,
                              void* d_out, int out_size) {
    KParams P;
    P.qs   = (const float*)d_in[0];
    P.ents = (const float*)d_in[1];
    P.em   = (const unsigned char*)d_in[2];
    for (int i = 0; i < 14; ++i) P.w[i] = (const float*)d_in[3 + i];
    P.out = (float*)d_out;

    cudaFuncSetAttribute(mixer_kernel, cudaFuncAttributeMaxDynamicSharedMemorySize, SMEM_BYTES);

    dim3 pgrid((128 * 16 + 255) / 256, 8);
    prep_kernel<<<pgrid, 256>>>(P);

    int nb = in_sizes[0] / NA;  // 1600
    mixer_kernel<<<nb, 256, SMEM_BYTES>>>(P);
}

// round 15
// speedup vs baseline: 1.1135x; 1.0360x over previous
#include <cuda_runtime.h>
#include <cuda_bf16.h>
#include <cstdint>

#define NA 16
#define NEN 128
#define ED 96
#define HE 128
#define MD 32
#define NH 4
#define HD 32
#define TSTRIDE 132   // fp32 stride (528B)
#define STRB 132      // u32 stride of bf16 tiles (528B)
#define SWST 132

// ---- smem float offsets ----
#define OFF_A    0        // A tile: 128 x 264 bf16 = 67584B
#define OFF_B    16896    // B tile: same (dead after v GEMM -> outw fp32 staging)
#define OFF_KV   33792    // 64 x 132 fp32 kT/vT (+ B(q) staging early); after attnV: s_out + s_x3
#define OFF_W    42240    // 64 x 132 softmax w; after attnV: fc2w staging (4096 fp32)
#define OFF_Q    50688    // 16 x 132 q; after logits: s_attn
#define OFF_EMF  52800
#define OFF_RM   52928
#define OFF_W1   52944
#define OFF_FLAG 52960
#define SMEM_FLOATS 52968
#define SMEM_BYTES (SMEM_FLOATS * 4)

#define TILE_U32 (128 * 132)

struct KParams {
    const float* qs;
    const float* ents;
    const unsigned char* em;
    const float* w[14];
    float* out;
};

__device__ uint32_t g_wt[8 * TILE_U32];

static __device__ __forceinline__ void split2(float a, float b, uint32_t& hi, uint32_t& lo) {
    __nv_bfloat16 ha = __float2bfloat16(a), hb = __float2bfloat16(b);
    float ra = a - __bfloat162float(ha), rb = b - __bfloat162float(hb);
    __nv_bfloat16 la = __float2bfloat16(ra), lb = __float2bfloat16(rb);
    hi = (uint32_t)__bfloat16_as_ushort(ha) | ((uint32_t)__bfloat16_as_ushort(hb) << 16);
    lo = (uint32_t)__bfloat16_as_ushort(la) | ((uint32_t)__bfloat16_as_ushort(lb) << 16);
}

static __device__ __forceinline__ float2 ffma2(float2 a, float2 b, float2 c) {
    unsigned long long au = *reinterpret_cast<unsigned long long*>(&a);
    unsigned long long bu = *reinterpret_cast<unsigned long long*>(&b);
    unsigned long long cu = *reinterpret_cast<unsigned long long*>(&c);
    asm("fma.rn.f32x2 %0, %1, %2, %0;" : "+l"(cu) : "l"(au), "l"(bu));
    return *reinterpret_cast<float2*>(&cu);
}

static __device__ __forceinline__ void ldmat4(uint32_t (&r)[4], uint32_t addr) {
    asm volatile("ldmatrix.sync.aligned.m8n8.x4.shared.b16 {%0,%1,%2,%3}, [%4];"
        : "=r"(r[0]), "=r"(r[1]), "=r"(r[2]), "=r"(r[3]) : "r"(addr));
}

static __device__ __forceinline__ void mma16816(float (&d)[4], const uint32_t (&a)[4],
                                                uint32_t b0, uint32_t b1) {
    asm volatile("mma.sync.aligned.m16n8k16.row.col.f32.bf16.bf16.f32 "
        "{%0,%1,%2,%3}, {%4,%5,%6,%7}, {%8,%9}, {%0,%1,%2,%3};"
        : "+f"(d[0]), "+f"(d[1]), "+f"(d[2]), "+f"(d[3])
        : "r"(a[0]), "r"(a[1]), "r"(a[2]), "r"(a[3]), "r"(b0), "r"(b1));
}

static __device__ __forceinline__ void cp_async16(uint32_t saddr, const void* g) {
    asm volatile("cp.async.cg.shared.global [%0], [%1], 16;" :: "r"(saddr), "l"(g));
}

static __device__ __forceinline__ void copyB_async(uint32_t base, const uint32_t* g, int tid) {
#pragma unroll 1
    for (int i = tid; i < TILE_U32 / 4; i += 256)
        cp_async16(base + (uint32_t)i * 16u, g + i * 4);
    asm volatile("cp.async.commit_group;" ::: "memory");
}
#define CP_WAIT0() asm volatile("cp.async.wait_group 0;" ::: "memory")
#define CP_WAIT1() asm volatile("cp.async.wait_group 1;" ::: "memory")

// Fused split-3 bf16 GEMM, warp tile 32x64: per k-step load A_hi/A_lo/B_hi/B_lo
// once (12 LDSM) and issue all 3 passes (48 MMA): hi*hi + lo*hi + hi*lo.
template<int K>
static __device__ __forceinline__ void gemm_mma(uint32_t aL, uint32_t bL, float (&acc)[2][8][4]) {
#pragma unroll
    for (int i = 0; i < 2; ++i)
#pragma unroll
        for (int j = 0; j < 8; ++j)
#pragma unroll
            for (int r = 0; r < 4; ++r) acc[i][j][r] = 0.f;
#pragma unroll
    for (int kb = 0; kb < K * 2; kb += 32) {
        uint32_t aH[2][4], aLo[2][4], bH[4][4], bLo[4][4];
        ldmat4(aH[0],  aL + kb);
        ldmat4(aH[1],  aL + 16u * 528u + kb);
        ldmat4(aLo[0], aL + (uint32_t)(K * 2) + kb);
        ldmat4(aLo[1], aL + 16u * 528u + (uint32_t)(K * 2) + kb);
#pragma unroll
        for (int nj = 0; nj < 4; ++nj) {
            ldmat4(bH[nj],  bL + (uint32_t)nj * 16u * 528u + kb);
            ldmat4(bLo[nj], bL + (uint32_t)nj * 16u * 528u + (uint32_t)(K * 2) + kb);
        }
#pragma unroll
        for (int mi = 0; mi < 2; ++mi)
#pragma unroll
            for (int nj = 0; nj < 4; ++nj) {
                mma16816(acc[mi][2 * nj],     aH[mi],  bH[nj][0],  bH[nj][1]);
                mma16816(acc[mi][2 * nj + 1], aH[mi],  bH[nj][2],  bH[nj][3]);
                mma16816(acc[mi][2 * nj],     aLo[mi], bH[nj][0],  bH[nj][1]);
                mma16816(acc[mi][2 * nj + 1], aLo[mi], bH[nj][2],  bH[nj][3]);
                mma16816(acc[mi][2 * nj],     aH[mi],  bLo[nj][0], bLo[nj][1]);
                mma16816(acc[mi][2 * nj + 1], aH[mi],  bLo[nj][2], bLo[nj][3]);
            }
    }
}

// ---- prep kernel: split weights into tile-image layout ----
__global__ void prep_kernel(KParams P) {
    const int t = blockIdx.y;
    const int p = t >> 2, ch = t & 3;
    const float* W; int ldb, KP;
    if (ch == 0) { W = P.w[p * 7 + 0]; ldb = HE;     KP = ED / 2; }
    else         { W = P.w[p * 7 + 2] + (ch - 1) * HE; ldb = 3 * HE; KP = 64; }
    uint32_t* dst = g_wt + t * TILE_U32;
    const int nkpb = KP >> 2;
    int idx = blockIdx.x * blockDim.x + threadIdx.x;
    if (idx >= 128 * nkpb) return;
    int n = idx / nkpb, kpb = idx % nkpb;
    uint32_t hi[4], lo[4];
#pragma unroll
    for (int j = 0; j < 4; ++j) {
        int kp = kpb * 4 + j;
        float w0 = __ldg(W + (size_t)(2 * kp) * ldb + n);
        float w1 = __ldg(W + (size_t)(2 * kp + 1) * ldb + n);
        split2(w0, w1, hi[j], lo[j]);
    }
    *reinterpret_cast<uint4*>(dst + n * STRB + kpb * 4)      = make_uint4(hi[0], hi[1], hi[2], hi[3]);
    *reinterpret_cast<uint4*>(dst + n * STRB + KP + kpb * 4) = make_uint4(lo[0], lo[1], lo[2], lo[3]);
}

__global__ void __launch_bounds__(256, 1)
mixer_kernel(KParams P) {
    extern __shared__ float smem[];
    uint32_t* Au    = reinterpret_cast<uint32_t*>(smem + OFF_A);
    float*    s_kv  = smem + OFF_KV;
    float*    s_w   = smem + OFF_W;
    float*    s_q   = smem + OFF_Q;
    float*    s_emf = smem + OFF_EMF;
    float*    s_rm  = smem + OFF_RM;
    float*    s_w1m = smem + OFF_W1;
    float*    s_flag= smem + OFF_FLAG;
    float*    s_attn= smem + OFF_Q;          // reuses q region (dead after logits)
    float*    s_out = smem + OFF_KV;         // reuses kv region (dead after attnV)
    float*    s_x3  = smem + OFF_KV + 2112;
    float*    s_f2w = smem + OFF_W;          // reuses w region (dead after attnV)
    float*    s_ow  = smem + OFF_B;          // outw fp32 staging (B dead after v GEMM)

    __shared__ int s_wide;

    const int b    = blockIdx.x;
    const int tid  = threadIdx.x;
    const int lane = tid & 31;
    const int warp = tid >> 5;

    // main GEMM: 4 m-warps x 2 n-warps, warp tile 32x64
    const int mw = warp & 3, nw = warp >> 2;
    const int m0 = mw * 32, n0 = nw * 64;

    const int q16 = tid & 15;
    const int cg  = tid >> 4;
    const int cq0 = cg * 8;

    uint32_t smem_u32;
    asm("{ .reg .u64 t; cvta.to.shared.u64 t, %1; cvt.u32.u64 %0, t; }"
        : "=r"(smem_u32) : "l"(smem));
    const uint32_t aBase  = smem_u32 + OFF_A * 4;
    const uint32_t bBase  = smem_u32 + OFF_B * 4;
    const uint32_t qwBase = smem_u32 + OFF_KV * 4;  // B(q) staging tile
    const uint32_t aL = aBase + (uint32_t)(m0 + (lane & 15)) * 528u + (uint32_t)(lane >> 4) * 16u;
    const uint32_t bL = bBase + (uint32_t)(n0 + (lane & 7) + ((lane & 16) >> 1)) * 528u
                              + (uint32_t)((lane >> 3) & 1) * 16u;
    // small q GEMM addressing: A rows 0..15, B(q) cols warp*16..+15
    const uint32_t aQ = aBase + (uint32_t)(lane & 15) * 528u + (uint32_t)(lane >> 4) * 16u;
    const uint32_t bQ = qwBase + (uint32_t)(warp * 16 + (lane & 7) + ((lane & 16) >> 1)) * 528u
                               + (uint32_t)((lane >> 3) & 1) * 16u;

    // ---- mask dtype probe ----
    if (tid == 0) s_wide = 1;
    __syncthreads();
    {
        const unsigned* mwp = reinterpret_cast<const unsigned*>(P.em);
        bool ok = true;
#pragma unroll
        for (int s = 0; s < 4; ++s) {
            unsigned w = __ldg(mwp + tid + 256 * s);
            ok = ok && (w == 0u || w == 1u || w == 0x3F800000u);
        }
        if (!ok) atomicAnd(&s_wide, 0);
    }
    __syncthreads();
    const bool wide = (s_wide != 0);

    if (tid < NEN) {
        bool m;
        if (wide) m = __ldg(reinterpret_cast<const unsigned*>(P.em) + (size_t)b * NEN + tid) != 0u;
        else      m = __ldg(P.em + (size_t)b * NEN + tid) != 0;
        s_emf[tid] = m ? 1.0f : 0.0f;
    }
    __syncthreads();
    if (tid == 0) {
        bool all = true;
#pragma unroll
        for (int i = 0; i < NEN; ++i) all = all && (s_emf[i] > 0.5f);
        s_flag[0] = all ? 1.0f : 0.0f;
    }
    __syncthreads();

    float acc[2][8][4];

    for (int p = 0; p < 2; ++p) {
        const float* fc1b = P.w[p * 7 + 1];
        const float* outw = P.w[p * 7 + 3];
        const float* outb = P.w[p * 7 + 4];
        const float* fc2w = P.w[p * 7 + 5];
        const float* fc2b = P.w[p * 7 + 6];
        const uint32_t* wt = g_wt + (p * 4) * TILE_U32;

        // ---- 1. cp.async B(fc1) + fill A (ent hi|lo) ----
        copyB_async(bBase, wt, tid);
        {
            const float2* eg = reinterpret_cast<const float2*>(P.ents + (size_t)b * NEN * ED);
            for (int i = tid; i < NEN * (ED / 2); i += 256) {
                int e = i / (ED / 2), d2 = i % (ED / 2);
                float2 v = __ldg(eg + i);
                uint32_t hi, lo;
                split2(v.x, v.y, hi, lo);
                Au[e * STRB + d2]            = hi;
                Au[e * STRB + (ED / 2) + d2] = lo;
            }
        }
        CP_WAIT0();
        __syncthreads();

        // ---- 2. fc1 GEMM ----
        gemm_mma<ED>(aL, bL, acc);
        __syncthreads();

        // ---- 3. cp.async B(q)->staging, B(k)->B  +  x1 epilogue into A ----
        copyB_async(qwBase, wt + TILE_U32, tid);
        copyB_async(bBase,  wt + 2 * TILE_U32, tid);
#pragma unroll
        for (int mi = 0; mi < 2; ++mi)
#pragma unroll
            for (int nj2 = 0; nj2 < 8; ++nj2) {
                int r = m0 + mi * 16 + (lane >> 2);
                int c = n0 + nj2 * 8 + 2 * (lane & 3);
                float bias0 = __ldg(fc1b + c), bias1 = __ldg(fc1b + c + 1);
                float x0 = fmaxf(acc[mi][nj2][0] + bias0, 0.f);
                float x1v = fmaxf(acc[mi][nj2][1] + bias1, 0.f);
                uint32_t hi, lo;
                split2(x0, x1v, hi, lo);
                Au[r * STRB + (c >> 1)]      = hi;
                Au[r * STRB + 64 + (c >> 1)] = lo;
                x0  = fmaxf(acc[mi][nj2][2] + bias0, 0.f);
                x1v = fmaxf(acc[mi][nj2][3] + bias1, 0.f);
                split2(x0, x1v, hi, lo);
                Au[(r + 8) * STRB + (c >> 1)]      = hi;
                Au[(r + 8) * STRB + 64 + (c >> 1)] = lo;
            }
        CP_WAIT0();
        __syncthreads();

        // ---- 4. small q GEMM (fused split-3; M=16, each warp 16x16) + k GEMM ----
        {
            float qacc[2][4];
#pragma unroll
            for (int j = 0; j < 2; ++j)
#pragma unroll
                for (int r = 0; r < 4; ++r) qacc[j][r] = 0.f;
#pragma unroll
            for (int kb = 0; kb < 256; kb += 32) {
                uint32_t aH[4], aLo[4], bH[4], bLo[4];
                ldmat4(aH,  aQ + kb);
                ldmat4(aLo, aQ + 256u + kb);
                ldmat4(bH,  bQ + kb);
                ldmat4(bLo, bQ + 256u + kb);
                mma16816(qacc[0], aH,  bH[0],  bH[1]);
                mma16816(qacc[1], aH,  bH[2],  bH[3]);
                mma16816(qacc[0], aLo, bH[0],  bH[1]);
                mma16816(qacc[1], aLo, bH[2],  bH[3]);
                mma16816(qacc[0], aH,  bLo[0], bLo[1]);
                mma16816(qacc[1], aH,  bLo[2], bLo[3]);
            }
            const float qs = 0.17677669529663687f;  // 1/sqrt(32)
            const int r = lane >> 2;
            const int cb = warp * 16 + 2 * (lane & 3);
#pragma unroll
            for (int nb = 0; nb < 2; ++nb) {
                const int c = cb + nb * 8;
                s_q[r * TSTRIDE + c]           = qacc[nb][0] * qs;
                s_q[r * TSTRIDE + c + 1]       = qacc[nb][1] * qs;
                s_q[(r + 8) * TSTRIDE + c]     = qacc[nb][2] * qs;
                s_q[(r + 8) * TSTRIDE + c + 1] = qacc[nb][3] * qs;
            }
        }
        gemm_mma<HE>(aL, bL, acc);   // k GEMM
        __syncthreads();

        // ---- 5. cp.async B(v) overlapped with kT writes + logits ----
        copyB_async(bBase, wt + 3 * TILE_U32, tid);
#pragma unroll
        for (int ph = 0; ph < 2; ++ph) {
            if (nw == ph) {
#pragma unroll
                for (int mi = 0; mi < 2; ++mi)
#pragma unroll
                    for (int nj2 = 0; nj2 < 8; ++nj2) {
                        int ent = m0 + mi * 16 + (lane >> 2);
                        int f = nj2 * 8 + 2 * (lane & 3);
                        s_kv[f * TSTRIDE + ent]           = acc[mi][nj2][0];
                        s_kv[(f + 1) * TSTRIDE + ent]     = acc[mi][nj2][1];
                        s_kv[f * TSTRIDE + ent + 8]       = acc[mi][nj2][2];
                        s_kv[(f + 1) * TSTRIDE + ent + 8] = acc[mi][nj2][3];
                    }
            }
            __syncthreads();
            {
                const int hl = warp >> 2;
                const int h  = ph * 2 + hl;
                const int e  = (warp & 3) * 32 + lane;
                float2 kvv[16];
#pragma unroll
                for (int d2 = 0; d2 < 16; ++d2) {
                    kvv[d2].x = s_kv[(hl * 32 + 2 * d2 + 0) * TSTRIDE + e];
                    kvv[d2].y = s_kv[(hl * 32 + 2 * d2 + 1) * TSTRIDE + e];
                }
#pragma unroll 2
                for (int q = 0; q < 16; ++q) {
                    const float* qrow = s_q + q * TSTRIDE + h * 32;
                    float2 a0 = make_float2(0.f, 0.f), a1 = make_float2(0.f, 0.f);
#pragma unroll
                    for (int d4 = 0; d4 < 8; ++d4) {
                        float4 q4 = *reinterpret_cast<const float4*>(qrow + d4 * 4);
                        a0 = ffma2(make_float2(q4.x, q4.y), kvv[d4 * 2 + 0], a0);
                        a1 = ffma2(make_float2(q4.z, q4.w), kvv[d4 * 2 + 1], a1);
                    }
                    s_w[(h * 16 + q) * SWST + e] = a0.x + a0.y + a1.x + a1.y;
                }
            }
            __syncthreads();
        }

        // ---- 6. masked softmax ----
        for (int it = 0; it < 8; ++it) {
            int pair = warp * 8 + it;
            int q = pair & 15;
            bool qmask = s_emf[q] > 0.5f;
            float lg[4];
#pragma unroll
            for (int j = 0; j < 4; ++j) {
                int k = lane + 32 * j;
                lg[j] = (qmask || s_emf[k] > 0.5f) ? -1e9f : s_w[pair * SWST + k];
            }
            float mx = fmaxf(fmaxf(lg[0], lg[1]), fmaxf(lg[2], lg[3]));
#pragma unroll
            for (int o = 16; o > 0; o >>= 1)
                mx = fmaxf(mx, __shfl_xor_sync(0xffffffffu, mx, o));
            float e[4];
            float sum = 0.f;
#pragma unroll
            for (int j = 0; j < 4; ++j) { e[j] = __expf(lg[j] - mx); sum += e[j]; }
#pragma unroll
            for (int o = 16; o > 0; o >>= 1)
                sum += __shfl_xor_sync(0xffffffffu, sum, o);
            bool allm = qmask || (s_flag[0] > 0.5f);
            float inv = allm ? 0.f : 1.f / sum;
#pragma unroll
            for (int j = 0; j < 4; ++j)
                s_w[pair * SWST + lane + 32 * j] = e[j] * inv;
        }
        CP_WAIT0();
        __syncthreads();

        // ---- 7. v GEMM ----
        gemm_mma<HE>(aL, bL, acc);
        __syncthreads();

        // ---- 7b. cp.async outw (fp32, 64KB) into dead B region — hides under attnV ----
        {
            const float4* og = reinterpret_cast<const float4*>(outw);
#pragma unroll 1
            for (int i = tid; i < (HE * HE) / 4; i += 256)
                cp_async16(bBase + (uint32_t)i * 16u, og + i);
            asm volatile("cp.async.commit_group;" ::: "memory");
        }

        // ---- 8. two-phase vT write + attnV (attn -> q region; q dead) ----
#pragma unroll
        for (int ph = 0; ph < 2; ++ph) {
            if (nw == ph) {
#pragma unroll
                for (int mi = 0; mi < 2; ++mi)
#pragma unroll
                    for (int nj2 = 0; nj2 < 8; ++nj2) {
                        int ent = m0 + mi * 16 + (lane >> 2);
                        int f = nj2 * 8 + 2 * (lane & 3);
                        s_kv[f * TSTRIDE + ent]           = acc[mi][nj2][0];
                        s_kv[(f + 1) * TSTRIDE + ent]     = acc[mi][nj2][1];
                        s_kv[f * TSTRIDE + ent + 8]       = acc[mi][nj2][2];
                        s_kv[(f + 1) * TSTRIDE + ent + 8] = acc[mi][nj2][3];
                    }
            }
            __syncthreads();
            if ((cg >> 3) == ph) {
                const int h  = cq0 >> 5;
                const int lf = cq0 - ph * 64;
                float2 a2[8];
#pragma unroll
                for (int j = 0; j < 8; ++j) a2[j] = make_float2(0.f, 0.f);
                const float* wrow = s_w + (h * 16 + q16) * SWST;
#pragma unroll 4
                for (int e0 = 0; e0 < NEN; e0 += 4) {
                    float4 w4 = *reinterpret_cast<const float4*>(wrow + e0);
                    float2 wlo = make_float2(w4.x, w4.y);
                    float2 whi = make_float2(w4.z, w4.w);
#pragma unroll
                    for (int jc = 0; jc < 8; ++jc) {
                        float4 v4 = *reinterpret_cast<const float4*>(&s_kv[(lf + jc) * TSTRIDE + e0]);
                        a2[jc] = ffma2(wlo, make_float2(v4.x, v4.y), a2[jc]);
                        a2[jc] = ffma2(whi, make_float2(v4.z, v4.w), a2[jc]);
                    }
                }
                float* ar = s_attn + q16 * TSTRIDE + cq0;
                *reinterpret_cast<float4*>(ar) = make_float4(
                    a2[0].x + a2[0].y, a2[1].x + a2[1].y, a2[2].x + a2[2].y, a2[3].x + a2[3].y);
                *reinterpret_cast<float4*>(ar + 4) = make_float4(
                    a2[4].x + a2[4].y, a2[5].x + a2[5].y, a2[6].x + a2[6].y, a2[7].x + a2[7].y);
            }
            __syncthreads();
        }

        // ---- 9. cp.async fc2w -> w region (s_w dead); wait outw; out-projection from smem ----
        {
            const float4* fg = reinterpret_cast<const float4*>(fc2w);
#pragma unroll 1
            for (int i = tid; i < (HE * MD) / 4; i += 256)
                cp_async16(smem_u32 + (uint32_t)(OFF_W + i * 4) * 4u, fg + i);
            asm volatile("cp.async.commit_group;" ::: "memory");
        }
        CP_WAIT1();       // outw staged
        __syncthreads();  // publish outw to all threads
        {
            float2 acc2[4];
#pragma unroll
            for (int j = 0; j < 4; ++j) acc2[j] = make_float2(0.f, 0.f);
            const float* Bo = s_ow + cq0;
#pragma unroll 4
            for (int k0 = 0; k0 < HE; k0 += 4) {
                float4 a4 = *reinterpret_cast<const float4*>(&s_attn[q16 * TSTRIDE + k0]);
                float av[4] = {a4.x, a4.y, a4.z, a4.w};
#pragma unroll
                for (int t = 0; t < 4; ++t) {
                    float4 b0 = *reinterpret_cast<const float4*>(Bo + (k0 + t) * HE);
                    float4 b1 = *reinterpret_cast<const float4*>(Bo + (k0 + t) * HE + 4);
                    float2 aa = make_float2(av[t], av[t]);
                    acc2[0] = ffma2(aa, make_float2(b0.x, b0.y), acc2[0]);
                    acc2[1] = ffma2(aa, make_float2(b0.z, b0.w), acc2[1]);
                    acc2[2] = ffma2(aa, make_float2(b1.x, b1.y), acc2[2]);
                    acc2[3] = ffma2(aa, make_float2(b1.z, b1.w), acc2[3]);
                }
            }
            float maskv = (s_emf[q16] > 0.5f) ? 0.f : 1.f;
            float4 ob0 = *reinterpret_cast<const float4*>(outb + cq0);
            float4 ob1 = *reinterpret_cast<const float4*>(outb + cq0 + 4);
            // s_out (kv region) disjoint from s_attn (q region): no extra barrier
            float* orow = s_out + q16 * TSTRIDE + cq0;
            *reinterpret_cast<float4*>(orow) = make_float4(
                (acc2[0].x + ob0.x) * maskv, (acc2[0].y + ob0.y) * maskv,
                (acc2[1].x + ob0.z) * maskv, (acc2[1].y + ob0.w) * maskv);
            *reinterpret_cast<float4*>(orow + 4) = make_float4(
                (acc2[2].x + ob1.x) * maskv, (acc2[2].y + ob1.y) * maskv,
                (acc2[3].x + ob1.z) * maskv, (acc2[3].y + ob1.w) * maskv);
        }
        CP_WAIT0();      // fc2w staged
        __syncthreads();

        // ---- 10. x3 = out @ fc2_w + fc2_b, masked (fc2w from smem) ----
        {
            const int m0x = cg * 2;
            float2 acc2 = make_float2(0.f, 0.f);
#pragma unroll 8
            for (int k0 = 0; k0 < HE; k0 += 4) {
                float4 a4 = *reinterpret_cast<const float4*>(&s_out[q16 * TSTRIDE + k0]);
                float av[4] = {a4.x, a4.y, a4.z, a4.w};
#pragma unroll
                for (int t = 0; t < 4; ++t) {
                    float2 bw = *reinterpret_cast<const float2*>(&s_f2w[(k0 + t) * MD + m0x]);
                    acc2 = ffma2(make_float2(av[t], av[t]), bw, acc2);
                }
            }
            float maskv = (s_emf[q16] > 0.5f) ? 0.f : 1.f;
            s_x3[q16 * MD + m0x]     = (acc2.x + fc2b[m0x])     * maskv;
            s_x3[q16 * MD + m0x + 1] = (acc2.y + fc2b[m0x + 1]) * maskv;
        }
        __syncthreads();

        if (tid < NA) {
            float s = 0.f;
#pragma unroll
            for (int m = 0; m < MD; ++m) s += s_x3[tid * MD + m];
            float rm = s * (1.f / MD);
            s_rm[tid] = rm;
            if (p == 0) s_w1m[tid] = rm;
        }
        __syncthreads();
    }

    if (tid == 0) {
        float vm = 0.f;
#pragma unroll
        for (int q = 0; q < NA; ++q) vm += s_rm[q];
        vm *= (1.f / NA);
        const float* qb = P.qs + (size_t)b * NA;
        float qt = 0.f;
#pragma unroll
        for (int a = 0; a < NA; ++a) qt += qb[a] * fabsf(s_w1m[a]);
        P.out[b] = qt + vm;
    }
}

extern "C" void kernel_launch(void* const* d_in, const int* in_sizes, int n_in,
                              void* d_out, int out_size) {
    KParams P;
    P.qs   = (const float*)d_in[0];
    P.ents = (const float*)d_in[1];
    P.em   = (const unsigned char*)d_in[2];
    for (int i = 0; i < 14; ++i) P.w[i] = (const float*)d_in[3 + i];
    P.out = (float*)d_out;

    cudaFuncSetAttribute(mixer_kernel, cudaFuncAttributeMaxDynamicSharedMemorySize, SMEM_BYTES);

    dim3 pgrid((128 * 16 + 255) / 256, 8);
    prep_kernel<<<pgrid, 256>>>(P);

    int nb = in_sizes[0] / NA;  // 1600
    mixer_kernel<<<nb, 256, SMEM_BYTES>>>(P);
}

// round 16
// speedup vs baseline: 1.1544x; 1.0367x over previous
#include <cuda_runtime.h>
#include <cuda_bf16.h>
#include <cstdint>

#define NA 16
#define NEN 128
#define ED 96
#define HE 128
#define MD 32
#define NH 4
#define HD 32
#define TSTRIDE 132   // fp32 stride (528B)
#define STRB 132      // u32 stride of bf16 tiles (528B)
#define SWST 132

// ---- smem float offsets ----
#define OFF_A    0        // A tile: x1; after v GEMM: vT-split B-format tile
#define OFF_B    16896    // B tile; dead after v GEMM -> outw fp32 staging
#define OFF_KV   33792    // kT fp32 / B(q) staging; after softmax: w-split tile; then s_out+s_x3
#define OFF_W    42240    // softmax w fp32; after repack: fc2w staging
#define OFF_Q    50688    // q; after logits: s_attn
#define OFF_EMF  52800
#define OFF_RM   52928
#define OFF_W1   52944
#define OFF_FLAG 52960
#define SMEM_FLOATS 52968
#define SMEM_BYTES (SMEM_FLOATS * 4)

#define TILE_U32 (128 * 132)

struct KParams {
    const float* qs;
    const float* ents;
    const unsigned char* em;
    const float* w[14];
    float* out;
};

__device__ uint32_t g_wt[8 * TILE_U32];

static __device__ __forceinline__ void split2(float a, float b, uint32_t& hi, uint32_t& lo) {
    __nv_bfloat16 ha = __float2bfloat16(a), hb = __float2bfloat16(b);
    float ra = a - __bfloat162float(ha), rb = b - __bfloat162float(hb);
    __nv_bfloat16 la = __float2bfloat16(ra), lb = __float2bfloat16(rb);
    hi = (uint32_t)__bfloat16_as_ushort(ha) | ((uint32_t)__bfloat16_as_ushort(hb) << 16);
    lo = (uint32_t)__bfloat16_as_ushort(la) | ((uint32_t)__bfloat16_as_ushort(lb) << 16);
}

static __device__ __forceinline__ void split1(float a, uint16_t& hi, uint16_t& lo) {
    __nv_bfloat16 ha = __float2bfloat16(a);
    float ra = a - __bfloat162float(ha);
    __nv_bfloat16 la = __float2bfloat16(ra);
    hi = __bfloat16_as_ushort(ha);
    lo = __bfloat16_as_ushort(la);
}

static __device__ __forceinline__ float2 ffma2(float2 a, float2 b, float2 c) {
    unsigned long long au = *reinterpret_cast<unsigned long long*>(&a);
    unsigned long long bu = *reinterpret_cast<unsigned long long*>(&b);
    unsigned long long cu = *reinterpret_cast<unsigned long long*>(&c);
    asm("fma.rn.f32x2 %0, %1, %2, %0;" : "+l"(cu) : "l"(au), "l"(bu));
    return *reinterpret_cast<float2*>(&cu);
}

static __device__ __forceinline__ void ldmat4(uint32_t (&r)[4], uint32_t addr) {
    asm volatile("ldmatrix.sync.aligned.m8n8.x4.shared.b16 {%0,%1,%2,%3}, [%4];"
        : "=r"(r[0]), "=r"(r[1]), "=r"(r[2]), "=r"(r[3]) : "r"(addr));
}

static __device__ __forceinline__ void mma16816(float (&d)[4], const uint32_t (&a)[4],
                                                uint32_t b0, uint32_t b1) {
    asm volatile("mma.sync.aligned.m16n8k16.row.col.f32.bf16.bf16.f32 "
        "{%0,%1,%2,%3}, {%4,%5,%6,%7}, {%8,%9}, {%0,%1,%2,%3};"
        : "+f"(d[0]), "+f"(d[1]), "+f"(d[2]), "+f"(d[3])
        : "r"(a[0]), "r"(a[1]), "r"(a[2]), "r"(a[3]), "r"(b0), "r"(b1));
}

static __device__ __forceinline__ void cp_async16(uint32_t saddr, const void* g) {
    asm volatile("cp.async.cg.shared.global [%0], [%1], 16;" :: "r"(saddr), "l"(g));
}

static __device__ __forceinline__ void copyB_async(uint32_t base, const uint32_t* g, int tid) {
#pragma unroll 1
    for (int i = tid; i < TILE_U32 / 4; i += 256)
        cp_async16(base + (uint32_t)i * 16u, g + i * 4);
    asm volatile("cp.async.commit_group;" ::: "memory");
}
#define CP_WAIT0() asm volatile("cp.async.wait_group 0;" ::: "memory")
#define CP_WAIT1() asm volatile("cp.async.wait_group 1;" ::: "memory")

// Fused split-3 bf16 GEMM, warp tile 32x64.
template<int K>
static __device__ __forceinline__ void gemm_mma(uint32_t aL, uint32_t bL, float (&acc)[2][8][4]) {
#pragma unroll
    for (int i = 0; i < 2; ++i)
#pragma unroll
        for (int j = 0; j < 8; ++j)
#pragma unroll
            for (int r = 0; r < 4; ++r) acc[i][j][r] = 0.f;
#pragma unroll
    for (int kb = 0; kb < K * 2; kb += 32) {
        uint32_t aH[2][4], aLo[2][4], bH[4][4], bLo[4][4];
        ldmat4(aH[0],  aL + kb);
        ldmat4(aH[1],  aL + 16u * 528u + kb);
        ldmat4(aLo[0], aL + (uint32_t)(K * 2) + kb);
        ldmat4(aLo[1], aL + 16u * 528u + (uint32_t)(K * 2) + kb);
#pragma unroll
        for (int nj = 0; nj < 4; ++nj) {
            ldmat4(bH[nj],  bL + (uint32_t)nj * 16u * 528u + kb);
            ldmat4(bLo[nj], bL + (uint32_t)nj * 16u * 528u + (uint32_t)(K * 2) + kb);
        }
#pragma unroll
        for (int mi = 0; mi < 2; ++mi)
#pragma unroll
            for (int nj = 0; nj < 4; ++nj) {
                mma16816(acc[mi][2 * nj],     aH[mi],  bH[nj][0],  bH[nj][1]);
                mma16816(acc[mi][2 * nj + 1], aH[mi],  bH[nj][2],  bH[nj][3]);
                mma16816(acc[mi][2 * nj],     aLo[mi], bH[nj][0],  bH[nj][1]);
                mma16816(acc[mi][2 * nj + 1], aLo[mi], bH[nj][2],  bH[nj][3]);
                mma16816(acc[mi][2 * nj],     aH[mi],  bLo[nj][0], bLo[nj][1]);
                mma16816(acc[mi][2 * nj + 1], aH[mi],  bLo[nj][2], bLo[nj][3]);
            }
    }
}

// Small fused split GEMM: M=16, per-warp 16x16 tile, K=128 (bytes 0..255 hi | 256..511 lo)
static __device__ __forceinline__ void gemm_small(uint32_t aA, uint32_t bA, float (&qacc)[2][4]) {
#pragma unroll
    for (int j = 0; j < 2; ++j)
#pragma unroll
        for (int r = 0; r < 4; ++r) qacc[j][r] = 0.f;
#pragma unroll
    for (int kb = 0; kb < 256; kb += 32) {
        uint32_t aH[4], aLo[4], bH[4], bLo[4];
        ldmat4(aH,  aA + kb);
        ldmat4(aLo, aA + 256u + kb);
        ldmat4(bH,  bA + kb);
        ldmat4(bLo, bA + 256u + kb);
        mma16816(qacc[0], aH,  bH[0],  bH[1]);
        mma16816(qacc[1], aH,  bH[2],  bH[3]);
        mma16816(qacc[0], aLo, bH[0],  bH[1]);
        mma16816(qacc[1], aLo, bH[2],  bH[3]);
        mma16816(qacc[0], aH,  bLo[0], bLo[1]);
        mma16816(qacc[1], aH,  bLo[2], bLo[3]);
    }
}

// ---- prep kernel: split weights into tile-image layout ----
__global__ void prep_kernel(KParams P) {
    const int t = blockIdx.y;
    const int p = t >> 2, ch = t & 3;
    const float* W; int ldb, KP;
    if (ch == 0) { W = P.w[p * 7 + 0]; ldb = HE;     KP = ED / 2; }
    else         { W = P.w[p * 7 + 2] + (ch - 1) * HE; ldb = 3 * HE; KP = 64; }
    uint32_t* dst = g_wt + t * TILE_U32;
    const int nkpb = KP >> 2;
    int idx = blockIdx.x * blockDim.x + threadIdx.x;
    if (idx >= 128 * nkpb) return;
    int n = idx / nkpb, kpb = idx % nkpb;
    uint32_t hi[4], lo[4];
#pragma unroll
    for (int j = 0; j < 4; ++j) {
        int kp = kpb * 4 + j;
        float w0 = __ldg(W + (size_t)(2 * kp) * ldb + n);
        float w1 = __ldg(W + (size_t)(2 * kp + 1) * ldb + n);
        split2(w0, w1, hi[j], lo[j]);
    }
    *reinterpret_cast<uint4*>(dst + n * STRB + kpb * 4)      = make_uint4(hi[0], hi[1], hi[2], hi[3]);
    *reinterpret_cast<uint4*>(dst + n * STRB + KP + kpb * 4) = make_uint4(lo[0], lo[1], lo[2], lo[3]);
}

__global__ void __launch_bounds__(256, 1)
mixer_kernel(KParams P) {
    extern __shared__ float smem[];
    uint32_t* Au    = reinterpret_cast<uint32_t*>(smem + OFF_A);
    uint16_t* At16  = reinterpret_cast<uint16_t*>(smem + OFF_A);
    uint32_t* kvU32 = reinterpret_cast<uint32_t*>(smem + OFF_KV);
    float*    s_kv  = smem + OFF_KV;
    float*    s_w   = smem + OFF_W;
    float*    s_q   = smem + OFF_Q;
    float*    s_emf = smem + OFF_EMF;
    float*    s_rm  = smem + OFF_RM;
    float*    s_w1m = smem + OFF_W1;
    float*    s_flag= smem + OFF_FLAG;
    float*    s_attn= smem + OFF_Q;          // reuses q region (dead after logits)
    float*    s_out = smem + OFF_KV;         // reuses kv region (dead after attn MMA)
    float*    s_x3  = smem + OFF_KV + 2112;
    float*    s_f2w = smem + OFF_W;          // reuses w region (dead after repack)
    float*    s_ow  = smem + OFF_B;          // outw fp32 staging (B dead after v GEMM)

    __shared__ int s_wide;

    const int b    = blockIdx.x;
    const int tid  = threadIdx.x;
    const int lane = tid & 31;
    const int warp = tid >> 5;

    // main GEMM: 4 m-warps x 2 n-warps, warp tile 32x64
    const int mw = warp & 3, nw = warp >> 2;
    const int m0 = mw * 32, n0 = nw * 64;

    const int q16 = tid & 15;
    const int cg  = tid >> 4;
    const int cq0 = cg * 8;

    uint32_t smem_u32;
    asm("{ .reg .u64 t; cvta.to.shared.u64 t, %1; cvt.u32.u64 %0, t; }"
        : "=r"(smem_u32) : "l"(smem));
    const uint32_t aBase  = smem_u32 + OFF_A * 4;
    const uint32_t bBase  = smem_u32 + OFF_B * 4;
    const uint32_t qwBase = smem_u32 + OFF_KV * 4;  // B(q) staging / w-split tile
    const uint32_t aL = aBase + (uint32_t)(m0 + (lane & 15)) * 528u + (uint32_t)(lane >> 4) * 16u;
    const uint32_t bL = bBase + (uint32_t)(n0 + (lane & 7) + ((lane & 16) >> 1)) * 528u
                              + (uint32_t)((lane >> 3) & 1) * 16u;
    // small GEMM addressing (q projection): A rows 0..15, B cols warp*16..+15
    const uint32_t aQ = aBase + (uint32_t)(lane & 15) * 528u + (uint32_t)(lane >> 4) * 16u;
    const uint32_t bQ = qwBase + (uint32_t)(warp * 16 + (lane & 7) + ((lane & 16) >> 1)) * 528u
                               + (uint32_t)((lane >> 3) & 1) * 16u;

    // ---- mask dtype probe ----
    if (tid == 0) s_wide = 1;
    __syncthreads();
    {
        const unsigned* mwp = reinterpret_cast<const unsigned*>(P.em);
        bool ok = true;
#pragma unroll
        for (int s = 0; s < 4; ++s) {
            unsigned w = __ldg(mwp + tid + 256 * s);
            ok = ok && (w == 0u || w == 1u || w == 0x3F800000u);
        }
        if (!ok) atomicAnd(&s_wide, 0);
    }
    __syncthreads();
    const bool wide = (s_wide != 0);

    if (tid < NEN) {
        bool m;
        if (wide) m = __ldg(reinterpret_cast<const unsigned*>(P.em) + (size_t)b * NEN + tid) != 0u;
        else      m = __ldg(P.em + (size_t)b * NEN + tid) != 0;
        s_emf[tid] = m ? 1.0f : 0.0f;
    }
    __syncthreads();
    if (tid == 0) {
        bool all = true;
#pragma unroll
        for (int i = 0; i < NEN; ++i) all = all && (s_emf[i] > 0.5f);
        s_flag[0] = all ? 1.0f : 0.0f;
    }
    __syncthreads();

    float acc[2][8][4];

    for (int p = 0; p < 2; ++p) {
        const float* fc1b = P.w[p * 7 + 1];
        const float* outw = P.w[p * 7 + 3];
        const float* outb = P.w[p * 7 + 4];
        const float* fc2w = P.w[p * 7 + 5];
        const float* fc2b = P.w[p * 7 + 6];
        const uint32_t* wt = g_wt + (p * 4) * TILE_U32;

        // ---- 1. cp.async B(fc1) + fill A (ent hi|lo) ----
        copyB_async(bBase, wt, tid);
        {
            const float2* eg = reinterpret_cast<const float2*>(P.ents + (size_t)b * NEN * ED);
            for (int i = tid; i < NEN * (ED / 2); i += 256) {
                int e = i / (ED / 2), d2 = i % (ED / 2);
                float2 v = __ldg(eg + i);
                uint32_t hi, lo;
                split2(v.x, v.y, hi, lo);
                Au[e * STRB + d2]            = hi;
                Au[e * STRB + (ED / 2) + d2] = lo;
            }
        }
        CP_WAIT0();
        __syncthreads();

        // ---- 2. fc1 GEMM ----
        gemm_mma<ED>(aL, bL, acc);
        __syncthreads();

        // ---- 3. cp.async B(q)->staging, B(k)->B  +  x1 epilogue into A ----
        copyB_async(qwBase, wt + TILE_U32, tid);
        copyB_async(bBase,  wt + 2 * TILE_U32, tid);
#pragma unroll
        for (int mi = 0; mi < 2; ++mi)
#pragma unroll
            for (int nj2 = 0; nj2 < 8; ++nj2) {
                int r = m0 + mi * 16 + (lane >> 2);
                int c = n0 + nj2 * 8 + 2 * (lane & 3);
                float bias0 = __ldg(fc1b + c), bias1 = __ldg(fc1b + c + 1);
                float x0 = fmaxf(acc[mi][nj2][0] + bias0, 0.f);
                float x1v = fmaxf(acc[mi][nj2][1] + bias1, 0.f);
                uint32_t hi, lo;
                split2(x0, x1v, hi, lo);
                Au[r * STRB + (c >> 1)]      = hi;
                Au[r * STRB + 64 + (c >> 1)] = lo;
                x0  = fmaxf(acc[mi][nj2][2] + bias0, 0.f);
                x1v = fmaxf(acc[mi][nj2][3] + bias1, 0.f);
                split2(x0, x1v, hi, lo);
                Au[(r + 8) * STRB + (c >> 1)]      = hi;
                Au[(r + 8) * STRB + 64 + (c >> 1)] = lo;
            }
        CP_WAIT0();
        __syncthreads();

        // ---- 4. small q GEMM + k GEMM ----
        {
            float qacc[2][4];
            gemm_small(aQ, bQ, qacc);
            const float qs = 0.17677669529663687f;  // 1/sqrt(32)
            const int r = lane >> 2;
            const int cb = warp * 16 + 2 * (lane & 3);
#pragma unroll
            for (int nb = 0; nb < 2; ++nb) {
                const int c = cb + nb * 8;
                s_q[r * TSTRIDE + c]           = qacc[nb][0] * qs;
                s_q[r * TSTRIDE + c + 1]       = qacc[nb][1] * qs;
                s_q[(r + 8) * TSTRIDE + c]     = qacc[nb][2] * qs;
                s_q[(r + 8) * TSTRIDE + c + 1] = qacc[nb][3] * qs;
            }
        }
        gemm_mma<HE>(aL, bL, acc);   // k GEMM
        __syncthreads();

        // ---- 5. cp.async B(v) overlapped with kT writes + logits ----
        copyB_async(bBase, wt + 3 * TILE_U32, tid);
#pragma unroll
        for (int ph = 0; ph < 2; ++ph) {
            if (nw == ph) {
#pragma unroll
                for (int mi = 0; mi < 2; ++mi)
#pragma unroll
                    for (int nj2 = 0; nj2 < 8; ++nj2) {
                        int ent = m0 + mi * 16 + (lane >> 2);
                        int f = nj2 * 8 + 2 * (lane & 3);
                        s_kv[f * TSTRIDE + ent]           = acc[mi][nj2][0];
                        s_kv[(f + 1) * TSTRIDE + ent]     = acc[mi][nj2][1];
                        s_kv[f * TSTRIDE + ent + 8]       = acc[mi][nj2][2];
                        s_kv[(f + 1) * TSTRIDE + ent + 8] = acc[mi][nj2][3];
                    }
            }
            __syncthreads();
            {
                const int hl = warp >> 2;
                const int h  = ph * 2 + hl;
                const int e  = (warp & 3) * 32 + lane;
                float2 kvv[16];
#pragma unroll
                for (int d2 = 0; d2 < 16; ++d2) {
                    kvv[d2].x = s_kv[(hl * 32 + 2 * d2 + 0) * TSTRIDE + e];
                    kvv[d2].y = s_kv[(hl * 32 + 2 * d2 + 1) * TSTRIDE + e];
                }
#pragma unroll 2
                for (int q = 0; q < 16; ++q) {
                    const float* qrow = s_q + q * TSTRIDE + h * 32;
                    float2 a0 = make_float2(0.f, 0.f), a1 = make_float2(0.f, 0.f);
#pragma unroll
                    for (int d4 = 0; d4 < 8; ++d4) {
                        float4 q4 = *reinterpret_cast<const float4*>(qrow + d4 * 4);
                        a0 = ffma2(make_float2(q4.x, q4.y), kvv[d4 * 2 + 0], a0);
                        a1 = ffma2(make_float2(q4.z, q4.w), kvv[d4 * 2 + 1], a1);
                    }
                    s_w[(h * 16 + q) * SWST + e] = a0.x + a0.y + a1.x + a1.y;
                }
            }
            __syncthreads();
        }

        // ---- 6. masked softmax ----
        for (int it = 0; it < 8; ++it) {
            int pair = warp * 8 + it;
            int q = pair & 15;
            bool qmask = s_emf[q] > 0.5f;
            float lg[4];
#pragma unroll
            for (int j = 0; j < 4; ++j) {
                int k = lane + 32 * j;
                lg[j] = (qmask || s_emf[k] > 0.5f) ? -1e9f : s_w[pair * SWST + k];
            }
            float mx = fmaxf(fmaxf(lg[0], lg[1]), fmaxf(lg[2], lg[3]));
#pragma unroll
            for (int o = 16; o > 0; o >>= 1)
                mx = fmaxf(mx, __shfl_xor_sync(0xffffffffu, mx, o));
            float e[4];
            float sum = 0.f;
#pragma unroll
            for (int j = 0; j < 4; ++j) { e[j] = __expf(lg[j] - mx); sum += e[j]; }
#pragma unroll
            for (int o = 16; o > 0; o >>= 1)
                sum += __shfl_xor_sync(0xffffffffu, sum, o);
            bool allm = qmask || (s_flag[0] > 0.5f);
            float inv = allm ? 0.f : 1.f / sum;
#pragma unroll
            for (int j = 0; j < 4; ++j)
                s_w[pair * SWST + lane + 32 * j] = e[j] * inv;
        }
        CP_WAIT0();
        __syncthreads();

        // ---- 7. v GEMM ----
        gemm_mma<HE>(aL, bL, acc);
        __syncthreads();

        // ---- 7b. cp.async outw into dead B region (group 1-of-2) ----
        {
            const float4* og = reinterpret_cast<const float4*>(outw);
#pragma unroll 1
            for (int i = tid; i < (HE * HE) / 4; i += 256)
                cp_async16(bBase + (uint32_t)i * 16u, og + i);
            asm volatile("cp.async.commit_group;" ::: "memory");
        }

        // ---- 8. vT split -> A region (B-format: row f, cols e hi|lo) + w repack -> kv tile ----
#pragma unroll
        for (int mi = 0; mi < 2; ++mi)
#pragma unroll
            for (int nj2 = 0; nj2 < 8; ++nj2) {
                int ent = m0 + mi * 16 + (lane >> 2);
                int f = n0 + nj2 * 8 + 2 * (lane & 3);
                uint16_t hi, lo;
                split1(acc[mi][nj2][0], hi, lo);
                At16[f * 264 + ent] = hi;       At16[f * 264 + 128 + ent] = lo;
                split1(acc[mi][nj2][1], hi, lo);
                At16[(f + 1) * 264 + ent] = hi; At16[(f + 1) * 264 + 128 + ent] = lo;
                split1(acc[mi][nj2][2], hi, lo);
                At16[f * 264 + ent + 8] = hi;   At16[f * 264 + 128 + ent + 8] = lo;
                split1(acc[mi][nj2][3], hi, lo);
                At16[(f + 1) * 264 + ent + 8] = hi; At16[(f + 1) * 264 + 128 + ent + 8] = lo;
            }
        // w repack: 64 rows x 64 u32-pairs (kT dead)
#pragma unroll 2
        for (int i = tid; i < 64 * 64; i += 256) {
            int row = i >> 6, pe = i & 63;
            float w0 = s_w[row * SWST + 2 * pe];
            float w1 = s_w[row * SWST + 2 * pe + 1];
            uint32_t hi, lo;
            split2(w0, w1, hi, lo);
            kvU32[row * 132 + pe]      = hi;
            kvU32[row * 132 + 64 + pe] = lo;
        }
        __syncthreads();

        // ---- 9. attnV MMA (per warp: head h=warp>>1, f-half=warp&1, 16x16 tile) ----
        //      + cp.async fc2w -> W region (s_w dead after repack)
        {
            const float4* fg = reinterpret_cast<const float4*>(fc2w);
#pragma unroll 1
            for (int i = tid; i < (HE * MD) / 4; i += 256)
                cp_async16(smem_u32 + (uint32_t)(OFF_W + i * 4) * 4u, fg + i);
            asm volatile("cp.async.commit_group;" ::: "memory");
        }
        {
            const int h = warp >> 1, nf = warp & 1;
            const uint32_t aA = qwBase + (uint32_t)(h * 16 + (lane & 15)) * 528u
                                       + (uint32_t)(lane >> 4) * 16u;
            const uint32_t bA = aBase + (uint32_t)(h * 32 + nf * 16 + (lane & 7) + ((lane & 16) >> 1)) * 528u
                                      + (uint32_t)((lane >> 3) & 1) * 16u;
            float qacc[2][4];
            gemm_small(aA, bA, qacc);
            const int r = lane >> 2;
            const int cb = h * 32 + nf * 16 + 2 * (lane & 3);
#pragma unroll
            for (int nb = 0; nb < 2; ++nb) {
                const int c = cb + nb * 8;
                s_attn[r * TSTRIDE + c]           = qacc[nb][0];
                s_attn[r * TSTRIDE + c + 1]       = qacc[nb][1];
                s_attn[(r + 8) * TSTRIDE + c]     = qacc[nb][2];
                s_attn[(r + 8) * TSTRIDE + c + 1] = qacc[nb][3];
            }
        }
        CP_WAIT1();       // outw staged
        __syncthreads();  // attn published; w-split tile dead -> s_out may overwrite kv

        // ---- 10. out = attn @ out_w + out_b, masked (outw from smem) ----
        {
            float2 acc2[4];
#pragma unroll
            for (int j = 0; j < 4; ++j) acc2[j] = make_float2(0.f, 0.f);
            const float* Bo = s_ow + cq0;
#pragma unroll 4
            for (int k0 = 0; k0 < HE; k0 += 4) {
                float4 a4 = *reinterpret_cast<const float4*>(&s_attn[q16 * TSTRIDE + k0]);
                float av[4] = {a4.x, a4.y, a4.z, a4.w};
#pragma unroll
                for (int t = 0; t < 4; ++t) {
                    float4 b0 = *reinterpret_cast<const float4*>(Bo + (k0 + t) * HE);
                    float4 b1 = *reinterpret_cast<const float4*>(Bo + (k0 + t) * HE + 4);
                    float2 aa = make_float2(av[t], av[t]);
                    acc2[0] = ffma2(aa, make_float2(b0.x, b0.y), acc2[0]);
                    acc2[1] = ffma2(aa, make_float2(b0.z, b0.w), acc2[1]);
                    acc2[2] = ffma2(aa, make_float2(b1.x, b1.y), acc2[2]);
                    acc2[3] = ffma2(aa, make_float2(b1.z, b1.w), acc2[3]);
                }
            }
            float maskv = (s_emf[q16] > 0.5f) ? 0.f : 1.f;
            float4 ob0 = *reinterpret_cast<const float4*>(outb + cq0);
            float4 ob1 = *reinterpret_cast<const float4*>(outb + cq0 + 4);
            float* orow = s_out + q16 * TSTRIDE + cq0;
            *reinterpret_cast<float4*>(orow) = make_float4(
                (acc2[0].x + ob0.x) * maskv, (acc2[0].y + ob0.y) * maskv,
                (acc2[1].x + ob0.z) * maskv, (acc2[1].y + ob0.w) * maskv);
            *reinterpret_cast<float4*>(orow + 4) = make_float4(
                (acc2[2].x + ob1.x) * maskv, (acc2[2].y + ob1.y) * maskv,
                (acc2[3].x + ob1.z) * maskv, (acc2[3].y + ob1.w) * maskv);
        }
        CP_WAIT0();      // fc2w staged
        __syncthreads();

        // ---- 11. x3 = out @ fc2_w + fc2_b, masked (fc2w from smem) ----
        {
            const int m0x = cg * 2;
            float2 acc2 = make_float2(0.f, 0.f);
#pragma unroll 8
            for (int k0 = 0; k0 < HE; k0 += 4) {
                float4 a4 = *reinterpret_cast<const float4*>(&s_out[q16 * TSTRIDE + k0]);
                float av[4] = {a4.x, a4.y, a4.z, a4.w};
#pragma unroll
                for (int t = 0; t < 4; ++t) {
                    float2 bw = *reinterpret_cast<const float2*>(&s_f2w[(k0 + t) * MD + m0x]);
                    acc2 = ffma2(make_float2(av[t], av[t]), bw, acc2);
                }
            }
            float maskv = (s_emf[q16] > 0.5f) ? 0.f : 1.f;
            s_x3[q16 * MD + m0x]     = (acc2.x + fc2b[m0x])     * maskv;
            s_x3[q16 * MD + m0x + 1] = (acc2.y + fc2b[m0x + 1]) * maskv;
        }
        __syncthreads();

        if (tid < NA) {
            float s = 0.f;
#pragma unroll
            for (int m = 0; m < MD; ++m) s += s_x3[tid * MD + m];
            float rm = s * (1.f / MD);
            s_rm[tid] = rm;
            if (p == 0) s_w1m[tid] = rm;
        }
        __syncthreads();
    }

    if (tid == 0) {
        float vm = 0.f;
#pragma unroll
        for (int q = 0; q < NA; ++q) vm += s_rm[q];
        vm *= (1.f / NA);
        const float* qb = P.qs + (size_t)b * NA;
        float qt = 0.f;
#pragma unroll
        for (int a = 0; a < NA; ++a) qt += qb[a] * fabsf(s_w1m[a]);
        P.out[b] = qt + vm;
    }
}

extern "C" void kernel_launch(void* const* d_in, const int* in_sizes, int n_in,
                              void* d_out, int out_size) {
    KParams P;
    P.qs   = (const float*)d_in[0];
    P.ents = (const float*)d_in[1];
    P.em   = (const unsigned char*)d_in[2];
    for (int i = 0; i < 14; ++i) P.w[i] = (const float*)d_in[3 + i];
    P.out = (float*)d_out;

    cudaFuncSetAttribute(mixer_kernel, cudaFuncAttributeMaxDynamicSharedMemorySize, SMEM_BYTES);

    dim3 pgrid((128 * 16 + 255) / 256, 8);
    prep_kernel<<<pgrid, 256>>>(P);

    int nb = in_sizes[0] / NA;  // 1600
    mixer_kernel<<<nb, 256, SMEM_BYTES>>>(P);
}

// round 17
// speedup vs baseline: 1.2343x; 1.0692x over previous
#include <cuda_runtime.h>
#include <cuda_bf16.h>
#include <cstdint>

#define NA 16
#define NEN 128
#define ED 96
#define HE 128
#define MD 32
#define NH 4
#define HD 32
#define TSTRIDE 132
#define STRB 132
#define SWST 132

// ---- smem float offsets ----
#define OFF_A    0        // A: x1 tile; after v GEMM: vT-split (B-format)
#define OFF_B    16896    // B: weight tiles; after v GEMM: logits/softmax w; after repack: outw
#define OFF_KV   33792    // B(q) staging / k-split (spans KV+W); after repack: w-split; then s_out+s_x3
#define OFF_W    42240    // (part of k-split span); after repack: fc2w staging
#define OFF_Q    50688    // q-split bf16 (16x264 u16); after logits: s_attn
#define OFF_EMF  52800
#define OFF_RM   52928
#define OFF_W1   52944
#define OFF_FLAG 52960
#define SMEM_FLOATS 52968
#define SMEM_BYTES (SMEM_FLOATS * 4)

#define TILE_U32 (128 * 132)

struct KParams {
    const float* qs;
    const float* ents;
    const unsigned char* em;
    const float* w[14];
    float* out;
};

__device__ uint32_t g_wt[8 * TILE_U32];

static __device__ __forceinline__ void split2(float a, float b, uint32_t& hi, uint32_t& lo) {
    __nv_bfloat16 ha = __float2bfloat16(a), hb = __float2bfloat16(b);
    float ra = a - __bfloat162float(ha), rb = b - __bfloat162float(hb);
    __nv_bfloat16 la = __float2bfloat16(ra), lb = __float2bfloat16(rb);
    hi = (uint32_t)__bfloat16_as_ushort(ha) | ((uint32_t)__bfloat16_as_ushort(hb) << 16);
    lo = (uint32_t)__bfloat16_as_ushort(la) | ((uint32_t)__bfloat16_as_ushort(lb) << 16);
}

static __device__ __forceinline__ void split1(float a, uint16_t& hi, uint16_t& lo) {
    __nv_bfloat16 ha = __float2bfloat16(a);
    float ra = a - __bfloat162float(ha);
    __nv_bfloat16 la = __float2bfloat16(ra);
    hi = __bfloat16_as_ushort(ha);
    lo = __bfloat16_as_ushort(la);
}

static __device__ __forceinline__ float2 ffma2(float2 a, float2 b, float2 c) {
    unsigned long long au = *reinterpret_cast<unsigned long long*>(&a);
    unsigned long long bu = *reinterpret_cast<unsigned long long*>(&b);
    unsigned long long cu = *reinterpret_cast<unsigned long long*>(&c);
    asm("fma.rn.f32x2 %0, %1, %2, %0;" : "+l"(cu) : "l"(au), "l"(bu));
    return *reinterpret_cast<float2*>(&cu);
}

static __device__ __forceinline__ void ldmat4(uint32_t (&r)[4], uint32_t addr) {
    asm volatile("ldmatrix.sync.aligned.m8n8.x4.shared.b16 {%0,%1,%2,%3}, [%4];"
        : "=r"(r[0]), "=r"(r[1]), "=r"(r[2]), "=r"(r[3]) : "r"(addr));
}

static __device__ __forceinline__ void mma16816(float (&d)[4], const uint32_t (&a)[4],
                                                uint32_t b0, uint32_t b1) {
    asm volatile("mma.sync.aligned.m16n8k16.row.col.f32.bf16.bf16.f32 "
        "{%0,%1,%2,%3}, {%4,%5,%6,%7}, {%8,%9}, {%0,%1,%2,%3};"
        : "+f"(d[0]), "+f"(d[1]), "+f"(d[2]), "+f"(d[3])
        : "r"(a[0]), "r"(a[1]), "r"(a[2]), "r"(a[3]), "r"(b0), "r"(b1));
}

static __device__ __forceinline__ void cp_async16(uint32_t saddr, const void* g) {
    asm volatile("cp.async.cg.shared.global [%0], [%1], 16;" :: "r"(saddr), "l"(g));
}

static __device__ __forceinline__ void copyB_async(uint32_t base, const uint32_t* g, int tid) {
#pragma unroll 1
    for (int i = tid; i < TILE_U32 / 4; i += 256)
        cp_async16(base + (uint32_t)i * 16u, g + i * 4);
    asm volatile("cp.async.commit_group;" ::: "memory");
}
#define CP_WAIT0() asm volatile("cp.async.wait_group 0;" ::: "memory")
#define CP_WAIT1() asm volatile("cp.async.wait_group 1;" ::: "memory")

// Fused split-3 bf16 GEMM, warp tile 32x64.
template<int K>
static __device__ __forceinline__ void gemm_mma(uint32_t aL, uint32_t bL, float (&acc)[2][8][4]) {
#pragma unroll
    for (int i = 0; i < 2; ++i)
#pragma unroll
        for (int j = 0; j < 8; ++j)
#pragma unroll
            for (int r = 0; r < 4; ++r) acc[i][j][r] = 0.f;
#pragma unroll
    for (int kb = 0; kb < K * 2; kb += 32) {
        uint32_t aH[2][4], aLo[2][4], bH[4][4], bLo[4][4];
        ldmat4(aH[0],  aL + kb);
        ldmat4(aH[1],  aL + 16u * 528u + kb);
        ldmat4(aLo[0], aL + (uint32_t)(K * 2) + kb);
        ldmat4(aLo[1], aL + 16u * 528u + (uint32_t)(K * 2) + kb);
#pragma unroll
        for (int nj = 0; nj < 4; ++nj) {
            ldmat4(bH[nj],  bL + (uint32_t)nj * 16u * 528u + kb);
            ldmat4(bLo[nj], bL + (uint32_t)nj * 16u * 528u + (uint32_t)(K * 2) + kb);
        }
#pragma unroll
        for (int mi = 0; mi < 2; ++mi)
#pragma unroll
            for (int nj = 0; nj < 4; ++nj) {
                mma16816(acc[mi][2 * nj],     aH[mi],  bH[nj][0],  bH[nj][1]);
                mma16816(acc[mi][2 * nj + 1], aH[mi],  bH[nj][2],  bH[nj][3]);
                mma16816(acc[mi][2 * nj],     aLo[mi], bH[nj][0],  bH[nj][1]);
                mma16816(acc[mi][2 * nj + 1], aLo[mi], bH[nj][2],  bH[nj][3]);
                mma16816(acc[mi][2 * nj],     aH[mi],  bLo[nj][0], bLo[nj][1]);
                mma16816(acc[mi][2 * nj + 1], aH[mi],  bLo[nj][2], bLo[nj][3]);
            }
    }
}

// Small fused split GEMM: M=16, per-warp 16x16 tile, K=128 (bytes 0..255 hi | 256..511 lo)
static __device__ __forceinline__ void gemm_small(uint32_t aA, uint32_t bA, float (&qacc)[2][4]) {
#pragma unroll
    for (int j = 0; j < 2; ++j)
#pragma unroll
        for (int r = 0; r < 4; ++r) qacc[j][r] = 0.f;
#pragma unroll
    for (int kb = 0; kb < 256; kb += 32) {
        uint32_t aH[4], aLo[4], bH[4], bLo[4];
        ldmat4(aH,  aA + kb);
        ldmat4(aLo, aA + 256u + kb);
        ldmat4(bH,  bA + kb);
        ldmat4(bLo, bA + 256u + kb);
        mma16816(qacc[0], aH,  bH[0],  bH[1]);
        mma16816(qacc[1], aH,  bH[2],  bH[3]);
        mma16816(qacc[0], aLo, bH[0],  bH[1]);
        mma16816(qacc[1], aLo, bH[2],  bH[3]);
        mma16816(qacc[0], aH,  bLo[0], bLo[1]);
        mma16816(qacc[1], aH,  bLo[2], bLo[3]);
    }
}

// Tiny fused split GEMM: M=16, 16x16 tile, K=32 (hi at +0..63B, lo at +64..127B)
static __device__ __forceinline__ void gemm_k32(uint32_t aA, uint32_t bA, float (&qacc)[2][4]) {
#pragma unroll
    for (int j = 0; j < 2; ++j)
#pragma unroll
        for (int r = 0; r < 4; ++r) qacc[j][r] = 0.f;
#pragma unroll
    for (int kb = 0; kb < 64; kb += 32) {
        uint32_t aH[4], aLo[4], bH[4], bLo[4];
        ldmat4(aH,  aA + kb);
        ldmat4(aLo, aA + 64u + kb);
        ldmat4(bH,  bA + kb);
        ldmat4(bLo, bA + 64u + kb);
        mma16816(qacc[0], aH,  bH[0],  bH[1]);
        mma16816(qacc[1], aH,  bH[2],  bH[3]);
        mma16816(qacc[0], aLo, bH[0],  bH[1]);
        mma16816(qacc[1], aLo, bH[2],  bH[3]);
        mma16816(qacc[0], aH,  bLo[0], bLo[1]);
        mma16816(qacc[1], aH,  bLo[2], bLo[3]);
    }
}

// ---- prep kernel: split weights into tile-image layout ----
__global__ void prep_kernel(KParams P) {
    const int t = blockIdx.y;
    const int p = t >> 2, ch = t & 3;
    const float* W; int ldb, KP;
    if (ch == 0) { W = P.w[p * 7 + 0]; ldb = HE;     KP = ED / 2; }
    else         { W = P.w[p * 7 + 2] + (ch - 1) * HE; ldb = 3 * HE; KP = 64; }
    uint32_t* dst = g_wt + t * TILE_U32;
    const int nkpb = KP >> 2;
    int idx = blockIdx.x * blockDim.x + threadIdx.x;
    if (idx >= 128 * nkpb) return;
    int n = idx / nkpb, kpb = idx % nkpb;
    uint32_t hi[4], lo[4];
#pragma unroll
    for (int j = 0; j < 4; ++j) {
        int kp = kpb * 4 + j;
        float w0 = __ldg(W + (size_t)(2 * kp) * ldb + n);
        float w1 = __ldg(W + (size_t)(2 * kp + 1) * ldb + n);
        split2(w0, w1, hi[j], lo[j]);
    }
    *reinterpret_cast<uint4*>(dst + n * STRB + kpb * 4)      = make_uint4(hi[0], hi[1], hi[2], hi[3]);
    *reinterpret_cast<uint4*>(dst + n * STRB + KP + kpb * 4) = make_uint4(lo[0], lo[1], lo[2], lo[3]);
}

__global__ void __launch_bounds__(256, 1)
mixer_kernel(KParams P) {
    extern __shared__ float smem[];
    uint32_t* Au    = reinterpret_cast<uint32_t*>(smem + OFF_A);
    uint16_t* At16  = reinterpret_cast<uint16_t*>(smem + OFF_A);
    uint16_t* kv16  = reinterpret_cast<uint16_t*>(smem + OFF_KV);
    uint16_t* q16s  = reinterpret_cast<uint16_t*>(smem + OFF_Q);
    uint32_t* kvU32 = reinterpret_cast<uint32_t*>(smem + OFF_KV);
    float*    s_w   = smem + OFF_B;          // logits/softmax live in dead B region
    float*    s_emf = smem + OFF_EMF;
    float*    s_rm  = smem + OFF_RM;
    float*    s_w1m = smem + OFF_W1;
    float*    s_flag= smem + OFF_FLAG;
    float*    s_attn= smem + OFF_Q;          // after logits (q-split dead)
    float*    s_out = smem + OFF_KV;         // after attnV (w-split dead)
    float*    s_x3  = smem + OFF_KV + 2112;
    float*    s_f2w = smem + OFF_W;          // fc2w staging after repack
    float*    s_ow  = smem + OFF_B;          // outw staging after repack (w dead)

    __shared__ int s_wide;

    const int b    = blockIdx.x;
    const int tid  = threadIdx.x;
    const int lane = tid & 31;
    const int warp = tid >> 5;

    const int mw = warp & 3, nw = warp >> 2;
    const int m0 = mw * 32, n0 = nw * 64;

    const int q16 = tid & 15;
    const int cg  = tid >> 4;
    const int cq0 = cg * 8;

    uint32_t smem_u32;
    asm("{ .reg .u64 t; cvta.to.shared.u64 t, %1; cvt.u32.u64 %0, t; }"
        : "=r"(smem_u32) : "l"(smem));
    const uint32_t aBase  = smem_u32 + OFF_A * 4;
    const uint32_t bBase  = smem_u32 + OFF_B * 4;
    const uint32_t kvBase = smem_u32 + OFF_KV * 4;   // B(q) staging / k-split / w-split
    const uint32_t qBase  = smem_u32 + OFF_Q * 4;    // q-split
    const uint32_t aL = aBase + (uint32_t)(m0 + (lane & 15)) * 528u + (uint32_t)(lane >> 4) * 16u;
    const uint32_t bL = bBase + (uint32_t)(n0 + (lane & 7) + ((lane & 16) >> 1)) * 528u
                              + (uint32_t)((lane >> 3) & 1) * 16u;
    // small GEMM lane addressing fragments
    const uint32_t aRow16 = (uint32_t)(lane & 15) * 528u + (uint32_t)(lane >> 4) * 16u;
    const uint32_t bRowQ  = (uint32_t)((lane & 7) + ((lane & 16) >> 1)) * 528u
                          + (uint32_t)((lane >> 3) & 1) * 16u;

    // ---- mask dtype probe ----
    if (tid == 0) s_wide = 1;
    __syncthreads();
    {
        const unsigned* mwp = reinterpret_cast<const unsigned*>(P.em);
        bool ok = true;
#pragma unroll
        for (int s = 0; s < 4; ++s) {
            unsigned w = __ldg(mwp + tid + 256 * s);
            ok = ok && (w == 0u || w == 1u || w == 0x3F800000u);
        }
        if (!ok) atomicAnd(&s_wide, 0);
    }
    __syncthreads();
    const bool wide = (s_wide != 0);

    if (tid < NEN) {
        bool m;
        if (wide) m = __ldg(reinterpret_cast<const unsigned*>(P.em) + (size_t)b * NEN + tid) != 0u;
        else      m = __ldg(P.em + (size_t)b * NEN + tid) != 0;
        s_emf[tid] = m ? 1.0f : 0.0f;
    }
    __syncthreads();
    if (tid == 0) {
        bool all = true;
#pragma unroll
        for (int i = 0; i < NEN; ++i) all = all && (s_emf[i] > 0.5f);
        s_flag[0] = all ? 1.0f : 0.0f;
    }
    __syncthreads();

    float acc[2][8][4];

    for (int p = 0; p < 2; ++p) {
        const float* fc1b = P.w[p * 7 + 1];
        const float* outw = P.w[p * 7 + 3];
        const float* outb = P.w[p * 7 + 4];
        const float* fc2w = P.w[p * 7 + 5];
        const float* fc2b = P.w[p * 7 + 6];
        const uint32_t* wt = g_wt + (p * 4) * TILE_U32;

        // ---- 1. cp.async B(fc1) + fill A (ent hi|lo) ----
        copyB_async(bBase, wt, tid);
        {
            const float2* eg = reinterpret_cast<const float2*>(P.ents + (size_t)b * NEN * ED);
            for (int i = tid; i < NEN * (ED / 2); i += 256) {
                int e = i / (ED / 2), d2 = i % (ED / 2);
                float2 v = __ldg(eg + i);
                uint32_t hi, lo;
                split2(v.x, v.y, hi, lo);
                Au[e * STRB + d2]            = hi;
                Au[e * STRB + (ED / 2) + d2] = lo;
            }
        }
        CP_WAIT0();
        __syncthreads();

        // ---- 2. fc1 GEMM ----
        gemm_mma<ED>(aL, bL, acc);
        __syncthreads();

        // ---- 3. cp.async B(q)->KV staging, B(k)->B  +  x1 epilogue into A ----
        copyB_async(kvBase, wt + TILE_U32, tid);
        copyB_async(bBase,  wt + 2 * TILE_U32, tid);
#pragma unroll
        for (int mi = 0; mi < 2; ++mi)
#pragma unroll
            for (int nj2 = 0; nj2 < 8; ++nj2) {
                int r = m0 + mi * 16 + (lane >> 2);
                int c = n0 + nj2 * 8 + 2 * (lane & 3);
                float bias0 = __ldg(fc1b + c), bias1 = __ldg(fc1b + c + 1);
                float x0 = fmaxf(acc[mi][nj2][0] + bias0, 0.f);
                float x1v = fmaxf(acc[mi][nj2][1] + bias1, 0.f);
                uint32_t hi, lo;
                split2(x0, x1v, hi, lo);
                Au[r * STRB + (c >> 1)]      = hi;
                Au[r * STRB + 64 + (c >> 1)] = lo;
                x0  = fmaxf(acc[mi][nj2][2] + bias0, 0.f);
                x1v = fmaxf(acc[mi][nj2][3] + bias1, 0.f);
                split2(x0, x1v, hi, lo);
                Au[(r + 8) * STRB + (c >> 1)]      = hi;
                Au[(r + 8) * STRB + 64 + (c >> 1)] = lo;
            }
        CP_WAIT0();
        __syncthreads();

        // ---- 4. small q GEMM -> q-split (A-format, scaled) + k GEMM ----
        {
            float qacc[2][4];
            gemm_small(aBase + aRow16, kvBase + (uint32_t)(warp * 16) * 528u + bRowQ, qacc);
            const float qs = 0.17677669529663687f;  // 1/sqrt(32)
            const int r = lane >> 2;
#pragma unroll
            for (int nb = 0; nb < 2; ++nb) {
                const int c = warp * 16 + 2 * (lane & 3) + nb * 8;
                const int h = c >> 5, d = c & 31;
                const int col = h * 64 + d;
                uint16_t hi, lo;
                split1(qacc[nb][0] * qs, hi, lo);
                q16s[r * 264 + col] = hi;            q16s[r * 264 + col + 32] = lo;
                split1(qacc[nb][1] * qs, hi, lo);
                q16s[r * 264 + col + 1] = hi;        q16s[r * 264 + col + 33] = lo;
                split1(qacc[nb][2] * qs, hi, lo);
                q16s[(r + 8) * 264 + col] = hi;      q16s[(r + 8) * 264 + col + 32] = lo;
                split1(qacc[nb][3] * qs, hi, lo);
                q16s[(r + 8) * 264 + col + 1] = hi;  q16s[(r + 8) * 264 + col + 33] = lo;
            }
        }
        gemm_mma<HE>(aL, bL, acc);   // k GEMM
        __syncthreads();

        // ---- 5. cp.async B(v)->B + k epilogue -> k-split (B-format per head) ----
        copyB_async(bBase, wt + 3 * TILE_U32, tid);
#pragma unroll
        for (int mi = 0; mi < 2; ++mi)
#pragma unroll
            for (int nj2 = 0; nj2 < 8; ++nj2) {
                int ent = m0 + mi * 16 + (lane >> 2);
                int f = n0 + nj2 * 8 + 2 * (lane & 3);
                const int h = f >> 5, d = f & 31;
                const int col = h * 64 + d;
                uint16_t hi, lo;
                split1(acc[mi][nj2][0], hi, lo);
                kv16[ent * 264 + col] = hi;           kv16[ent * 264 + col + 32] = lo;
                split1(acc[mi][nj2][1], hi, lo);
                kv16[ent * 264 + col + 1] = hi;       kv16[ent * 264 + col + 33] = lo;
                split1(acc[mi][nj2][2], hi, lo);
                kv16[(ent + 8) * 264 + col] = hi;     kv16[(ent + 8) * 264 + col + 32] = lo;
                split1(acc[mi][nj2][3], hi, lo);
                kv16[(ent + 8) * 264 + col + 1] = hi; kv16[(ent + 8) * 264 + col + 33] = lo;
            }
        CP_WAIT0();
        __syncthreads();

        // ---- 6. v GEMM ----
        gemm_mma<HE>(aL, bL, acc);
        __syncthreads();

        // ---- 7. v epilogue -> A region (vT-split B-format) + logits MMA -> s_w (B region) ----
#pragma unroll
        for (int mi = 0; mi < 2; ++mi)
#pragma unroll
            for (int nj2 = 0; nj2 < 8; ++nj2) {
                int ent = m0 + mi * 16 + (lane >> 2);
                int f = n0 + nj2 * 8 + 2 * (lane & 3);
                uint16_t hi, lo;
                split1(acc[mi][nj2][0], hi, lo);
                At16[f * 264 + ent] = hi;       At16[f * 264 + 128 + ent] = lo;
                split1(acc[mi][nj2][1], hi, lo);
                At16[(f + 1) * 264 + ent] = hi; At16[(f + 1) * 264 + 128 + ent] = lo;
                split1(acc[mi][nj2][2], hi, lo);
                At16[f * 264 + ent + 8] = hi;   At16[f * 264 + 128 + ent + 8] = lo;
                split1(acc[mi][nj2][3], hi, lo);
                At16[(f + 1) * 264 + ent + 8] = hi; At16[(f + 1) * 264 + 128 + ent + 8] = lo;
            }
        // logits: 32 tasks (h, et); per warp 4 tasks
#pragma unroll
        for (int t4 = 0; t4 < 4; ++t4) {
            const int task = warp + t4 * 8;
            const int h = task >> 3, et = task & 7;
            float qacc[2][4];
            gemm_k32(qBase + aRow16 + (uint32_t)(h * 128),
                     kvBase + (uint32_t)(et * 16) * 528u + bRowQ + (uint32_t)(h * 128), qacc);
            const int r = lane >> 2;
            const int cb = et * 16 + 2 * (lane & 3);
#pragma unroll
            for (int nb = 0; nb < 2; ++nb) {
                const int c = cb + nb * 8;
                s_w[(h * 16 + r) * SWST + c]           = qacc[nb][0];
                s_w[(h * 16 + r) * SWST + c + 1]       = qacc[nb][1];
                s_w[(h * 16 + r + 8) * SWST + c]       = qacc[nb][2];
                s_w[(h * 16 + r + 8) * SWST + c + 1]   = qacc[nb][3];
            }
        }
        __syncthreads();

        // ---- 8. masked softmax (in B region) ----
        for (int it = 0; it < 8; ++it) {
            int pair = warp * 8 + it;
            int q = pair & 15;
            bool qmask = s_emf[q] > 0.5f;
            float lg[4];
#pragma unroll
            for (int j = 0; j < 4; ++j) {
                int k = lane + 32 * j;
                lg[j] = (qmask || s_emf[k] > 0.5f) ? -1e9f : s_w[pair * SWST + k];
            }
            float mx = fmaxf(fmaxf(lg[0], lg[1]), fmaxf(lg[2], lg[3]));
#pragma unroll
            for (int o = 16; o > 0; o >>= 1)
                mx = fmaxf(mx, __shfl_xor_sync(0xffffffffu, mx, o));
            float e[4];
            float sum = 0.f;
#pragma unroll
            for (int j = 0; j < 4; ++j) { e[j] = __expf(lg[j] - mx); sum += e[j]; }
#pragma unroll
            for (int o = 16; o > 0; o >>= 1)
                sum += __shfl_xor_sync(0xffffffffu, sum, o);
            bool allm = qmask || (s_flag[0] > 0.5f);
            float inv = allm ? 0.f : 1.f / sum;
#pragma unroll
            for (int j = 0; j < 4; ++j)
                s_w[pair * SWST + lane + 32 * j] = e[j] * inv;
        }
        __syncthreads();

        // ---- 9. w repack -> KV region (k-split dead) ----
#pragma unroll 2
        for (int i = tid; i < 64 * 64; i += 256) {
            int row = i >> 6, pe = i & 63;
            float w0 = s_w[row * SWST + 2 * pe];
            float w1 = s_w[row * SWST + 2 * pe + 1];
            uint32_t hi, lo;
            split2(w0, w1, hi, lo);
            kvU32[row * 132 + pe]      = hi;
            kvU32[row * 132 + 64 + pe] = lo;
        }
        __syncthreads();

        // ---- 10. cp.async outw -> B (w dead), fc2w -> W; attnV MMA -> s_attn (Q region) ----
        {
            const float4* og = reinterpret_cast<const float4*>(outw);
#pragma unroll 1
            for (int i = tid; i < (HE * HE) / 4; i += 256)
                cp_async16(bBase + (uint32_t)i * 16u, og + i);
            asm volatile("cp.async.commit_group;" ::: "memory");
        }
        {
            const float4* fg = reinterpret_cast<const float4*>(fc2w);
#pragma unroll 1
            for (int i = tid; i < (HE * MD) / 4; i += 256)
                cp_async16(smem_u32 + (uint32_t)(OFF_W + i * 4) * 4u, fg + i);
            asm volatile("cp.async.commit_group;" ::: "memory");
        }
        {
            const int h = warp >> 1, nf = warp & 1;
            const uint32_t aA = kvBase + (uint32_t)(h * 16) * 528u + aRow16;
            const uint32_t bA = aBase + (uint32_t)(h * 32 + nf * 16) * 528u + bRowQ;
            float qacc[2][4];
            gemm_small(aA, bA, qacc);
            const int r = lane >> 2;
            const int cb = h * 32 + nf * 16 + 2 * (lane & 3);
#pragma unroll
            for (int nb = 0; nb < 2; ++nb) {
                const int c = cb + nb * 8;
                s_attn[r * TSTRIDE + c]           = qacc[nb][0];
                s_attn[r * TSTRIDE + c + 1]       = qacc[nb][1];
                s_attn[(r + 8) * TSTRIDE + c]     = qacc[nb][2];
                s_attn[(r + 8) * TSTRIDE + c + 1] = qacc[nb][3];
            }
        }
        CP_WAIT1();       // outw staged
        __syncthreads();  // attn published; w-split dead -> s_out may use KV

        // ---- 11. out = attn @ out_w + out_b, masked (outw from smem) ----
        {
            float2 acc2[4];
#pragma unroll
            for (int j = 0; j < 4; ++j) acc2[j] = make_float2(0.f, 0.f);
            const float* Bo = s_ow + cq0;
#pragma unroll 4
            for (int k0 = 0; k0 < HE; k0 += 4) {
                float4 a4 = *reinterpret_cast<const float4*>(&s_attn[q16 * TSTRIDE + k0]);
                float av[4] = {a4.x, a4.y, a4.z, a4.w};
#pragma unroll
                for (int t = 0; t < 4; ++t) {
                    float4 b0 = *reinterpret_cast<const float4*>(Bo + (k0 + t) * HE);
                    float4 b1 = *reinterpret_cast<const float4*>(Bo + (k0 + t) * HE + 4);
                    float2 aa = make_float2(av[t], av[t]);
                    acc2[0] = ffma2(aa, make_float2(b0.x, b0.y), acc2[0]);
                    acc2[1] = ffma2(aa, make_float2(b0.z, b0.w), acc2[1]);
                    acc2[2] = ffma2(aa, make_float2(b1.x, b1.y), acc2[2]);
                    acc2[3] = ffma2(aa, make_float2(b1.z, b1.w), acc2[3]);
                }
            }
            float maskv = (s_emf[q16] > 0.5f) ? 0.f : 1.f;
            float4 ob0 = *reinterpret_cast<const float4*>(outb + cq0);
            float4 ob1 = *reinterpret_cast<const float4*>(outb + cq0 + 4);
            float* orow = s_out + q16 * TSTRIDE + cq0;
            *reinterpret_cast<float4*>(orow) = make_float4(
                (acc2[0].x + ob0.x) * maskv, (acc2[0].y + ob0.y) * maskv,
                (acc2[1].x + ob0.z) * maskv, (acc2[1].y + ob0.w) * maskv);
            *reinterpret_cast<float4*>(orow + 4) = make_float4(
                (acc2[2].x + ob1.x) * maskv, (acc2[2].y + ob1.y) * maskv,
                (acc2[3].x + ob1.z) * maskv, (acc2[3].y + ob1.w) * maskv);
        }
        CP_WAIT0();      // fc2w staged
        __syncthreads();

        // ---- 12. x3 = out @ fc2_w + fc2_b, masked ----
        {
            const int m0x = cg * 2;
            float2 acc2 = make_float2(0.f, 0.f);
#pragma unroll 8
            for (int k0 = 0; k0 < HE; k0 += 4) {
                float4 a4 = *reinterpret_cast<const float4*>(&s_out[q16 * TSTRIDE + k0]);
                float av[4] = {a4.x, a4.y, a4.z, a4.w};
#pragma unroll
                for (int t = 0; t < 4; ++t) {
                    float2 bw = *reinterpret_cast<const float2*>(&s_f2w[(k0 + t) * MD + m0x]);
                    acc2 = ffma2(make_float2(av[t], av[t]), bw, acc2);
                }
            }
            float maskv = (s_emf[q16] > 0.5f) ? 0.f : 1.f;
            s_x3[q16 * MD + m0x]     = (acc2.x + fc2b[m0x])     * maskv;
            s_x3[q16 * MD + m0x + 1] = (acc2.y + fc2b[m0x + 1]) * maskv;
        }
        __syncthreads();

        if (tid < NA) {
            float s = 0.f;
#pragma unroll
            for (int m = 0; m < MD; ++m) s += s_x3[tid * MD + m];
            float rm = s * (1.f / MD);
            s_rm[tid] = rm;
            if (p == 0) s_w1m[tid] = rm;
        }
        __syncthreads();
    }

    if (tid == 0) {
        float vm = 0.f;
#pragma unroll
        for (int q = 0; q < NA; ++q) vm += s_rm[q];
        vm *= (1.f / NA);
        const float* qb = P.qs + (size_t)b * NA;
        float qt = 0.f;
#pragma unroll
        for (int a = 0; a < NA; ++a) qt += qb[a] * fabsf(s_w1m[a]);
        P.out[b] = qt + vm;
    }
}

extern "C" void kernel_launch(void* const* d_in, const int* in_sizes, int n_in,
                              void* d_out, int out_size) {
    KParams P;
    P.qs   = (const float*)d_in[0];
    P.ents = (const float*)d_in[1];
    P.em   = (const unsigned char*)d_in[2];
    for (int i = 0; i < 14; ++i) P.w[i] = (const float*)d_in[3 + i];
    P.out = (float*)d_out;

    cudaFuncSetAttribute(mixer_kernel, cudaFuncAttributeMaxDynamicSharedMemorySize, SMEM_BYTES);

    dim3 pgrid((128 * 16 + 255) / 256, 8);
    prep_kernel<<<pgrid, 256>>>(P);

    int nb = in_sizes[0] / NA;  // 1600
    mixer_kernel<<<nb, 256, SMEM_BYTES>>>(P);
}